// round 2
// baseline (speedup 1.0000x reference)
#include <cuda_runtime.h>

#define Bsz 512
#define Ssz 140
#define Hsz 512
#define Esz 256
#define Vsz 1000
#define Tsz 21
#define NDAYS 7
#define DLEN 20
#define H3 (3*Hsz)
#define SOS 2

// ---------------- device scratch (globals: allocation-free) ----------------
__device__ float g_h[2*Bsz*Hsz];          // double-buffered hidden state
__device__ float g_v[Bsz*Hsz];            // h @ Wa
__device__ float g_u[Bsz*Hsz];            // h_new @ Wa
__device__ float g_gh[Bsz*H3];            // h @ W_hh^T + b_hh
__device__ float g_GI[(size_t)Tsz*Bsz*H3];// precomputed input gates (66 MB)
__device__ int   g_idx[Tsz*Bsz];          // embedding row per (t,b)
__device__ float g_week[Bsz*NDAYS*Hsz];   // day contexts
__device__ float g_cc[Bsz*2*Hsz];         // [h_new, ctx]
__device__ float g_proj[Bsz*Hsz];         // tanh(cc @ wa_W^T)

// ---------------- index build: teacher-forced inputs ----------------
__global__ void build_idx_kernel(const int* __restrict__ label)
{
    int m = blockIdx.x * blockDim.x + threadIdx.x;
    if (m >= Tsz * Bsz) return;
    int t = m / Bsz, b = m % Bsz;
    g_idx[m] = (t == 0) ? SOS : label[b * (Tsz + 1) + (t - 1)];
}

// ---------------- generic fp32 GEMM: C = A (gathered) * op(B) ----------------
// 64x64 tile, BK=16, 128 threads, 8x4 micro-tile.
// transB=1: B is [N,K] row-major (C = A * B^T); transB=0: B is [K,N] row-major.
__global__ void sgemm64(const float* __restrict__ A, const float* __restrict__ Bm,
                        float* __restrict__ C, int M, int N, int K,
                        int transB, const float* __restrict__ bias, int doTanh,
                        const int* __restrict__ gidx, int ldc)
{
    __shared__ float As[16][64];
    __shared__ float Bs[16][64];
    int tid = threadIdx.x;
    int bm = blockIdx.y * 64, bn = blockIdx.x * 64;
    int tx = tid & 15, ty = tid >> 4;      // ty 0..7, tx 0..15

    float acc[8][4];
#pragma unroll
    for (int i = 0; i < 8; i++)
#pragma unroll
        for (int j = 0; j < 4; j++) acc[i][j] = 0.f;

    for (int k0 = 0; k0 < K; k0 += 16) {
        // A tile: 64 rows x 16 cols = 256 float4, 2 per thread
#pragma unroll
        for (int r = 0; r < 2; r++) {
            int idx = tid + r * 128;
            int row = idx >> 2, kc = (idx & 3) * 4;
            long abase = gidx ? (long)gidx[bm + row] * K : (long)(bm + row) * K;
            float4 a = *(const float4*)(A + abase + k0 + kc);
            As[kc + 0][row] = a.x; As[kc + 1][row] = a.y;
            As[kc + 2][row] = a.z; As[kc + 3][row] = a.w;
        }
        if (transB) {
#pragma unroll
            for (int r = 0; r < 2; r++) {
                int idx = tid + r * 128;
                int nl = idx >> 2, kc = (idx & 3) * 4;
                float4 bv = make_float4(0.f, 0.f, 0.f, 0.f);
                if (bn + nl < N)
                    bv = *(const float4*)(Bm + (long)(bn + nl) * K + k0 + kc);
                Bs[kc + 0][nl] = bv.x; Bs[kc + 1][nl] = bv.y;
                Bs[kc + 2][nl] = bv.z; Bs[kc + 3][nl] = bv.w;
            }
        } else {
#pragma unroll
            for (int r = 0; r < 2; r++) {
                int idx = tid + r * 128;
                int kl = idx >> 4, nc = (idx & 15) * 4;
                float4 bv = *(const float4*)(Bm + (long)(k0 + kl) * N + bn + nc);
                *(float4*)&Bs[kl][nc] = bv;
            }
        }
        __syncthreads();
#pragma unroll
        for (int kk = 0; kk < 16; kk++) {
            float4 b4 = *(const float4*)&Bs[kk][tx * 4];
            float4 a0 = *(const float4*)&As[kk][ty * 8];
            float4 a1 = *(const float4*)&As[kk][ty * 8 + 4];
            float av[8] = {a0.x, a0.y, a0.z, a0.w, a1.x, a1.y, a1.z, a1.w};
            float bv[4] = {b4.x, b4.y, b4.z, b4.w};
#pragma unroll
            for (int i = 0; i < 8; i++)
#pragma unroll
                for (int j = 0; j < 4; j++)
                    acc[i][j] += av[i] * bv[j];
        }
        __syncthreads();
    }
#pragma unroll
    for (int i = 0; i < 8; i++) {
        int m = bm + ty * 8 + i;
#pragma unroll
        for (int j = 0; j < 4; j++) {
            int n = bn + tx * 4 + j;
            if (n < N) {
                float vv = acc[i][j];
                if (bias) vv += bias[n];
                if (doTanh) vv = tanhf(vv);
                C[(long)m * ldc + n] = vv;
            }
        }
    }
}

// ---------------- day-level attention: week[b,d,:] ----------------
// sc[b,d,s] = v[b] . enc[b,d,s];  masked softmax over s (20);  weighted sum.
__global__ void day_attn_kernel(const float* __restrict__ enc,
                                const int* __restrict__ numpairs)
{
    __shared__ float sv[Hsz];
    __shared__ float tile[DLEN * Hsz];   // 40 KB
    __shared__ float ssc[DLEN];
    __shared__ float swt[DLEN];
    int b = blockIdx.x / NDAYS, d = blockIdx.x % NDAYS;
    int tid = threadIdx.x;               // 256

    for (int i = tid; i < Hsz; i += 256) sv[i] = g_v[b * Hsz + i];
    const float4* ep = (const float4*)(enc + ((long)b * Ssz + d * DLEN) * Hsz);
    float4* tp = (float4*)tile;
    for (int i = tid; i < DLEN * Hsz / 4; i += 256) tp[i] = ep[i];
    __syncthreads();

    int warp = tid >> 5, lane = tid & 31;
    for (int s = warp; s < DLEN; s += 8) {
        float p = 0.f;
        for (int h = lane; h < Hsz; h += 32) p += sv[h] * tile[s * Hsz + h];
#pragma unroll
        for (int o = 16; o > 0; o >>= 1) p += __shfl_xor_sync(0xffffffffu, p, o);
        if (lane == 0) ssc[s] = p;
    }
    __syncthreads();
    if (tid < 32) {
        float val = -1e30f;
        if (tid < DLEN)
            val = (numpairs[b * Ssz + d * DLEN + tid] != 0) ? ssc[tid] : -1e9f;
        float mx = val;
#pragma unroll
        for (int o = 16; o > 0; o >>= 1) mx = fmaxf(mx, __shfl_xor_sync(0xffffffffu, mx, o));
        float e = (tid < DLEN) ? expf(val - mx) : 0.f;
        float sm = e;
#pragma unroll
        for (int o = 16; o > 0; o >>= 1) sm += __shfl_xor_sync(0xffffffffu, sm, o);
        if (tid < DLEN) swt[tid] = e / sm;
    }
    __syncthreads();
    for (int h = tid; h < Hsz; h += 256) {
        float a = 0.f;
#pragma unroll
        for (int s = 0; s < DLEN; s++) a += swt[s] * tile[s * Hsz + h];
        g_week[((long)b * NDAYS + d) * Hsz + h] = a;
    }
}

// ---------------- GRU gates ----------------
__global__ void gru_gates_kernel(const float* __restrict__ hcur,
                                 float* __restrict__ hnew, int t)
{
    int i = blockIdx.x * blockDim.x + threadIdx.x;
    if (i >= Bsz * Hsz) return;
    int b = i >> 9, j = i & 511;
    const float* gi = g_GI + ((size_t)t * Bsz + b) * H3;
    const float* gh = g_gh + (size_t)b * H3;
    float ir = gi[j], iz = gi[j + Hsz], inn = gi[j + 2 * Hsz];
    float hr = gh[j], hz = gh[j + Hsz], hn = gh[j + 2 * Hsz];
    float r = 1.f / (1.f + expf(-(ir + hr)));
    float z = 1.f / (1.f + expf(-(iz + hz)));
    float n = tanhf(inn + r * hn);
    hnew[i] = (1.f - z) * n + z * hcur[i];
}

// ---------------- week-level attention + concat ----------------
__global__ void week_attn_kernel(const float* __restrict__ hnew)
{
    __shared__ float su[Hsz];
    __shared__ float sc[8];
    __shared__ float aw[8];
    int b = blockIdx.x, tid = threadIdx.x;  // 128 threads
    for (int i = tid; i < Hsz; i += 128) su[i] = g_u[b * Hsz + i];
    __syncthreads();
    int warp = tid >> 5, lane = tid & 31;
    for (int d = warp; d < NDAYS; d += 4) {
        const float* w = g_week + ((long)b * NDAYS + d) * Hsz;
        float p = 0.f;
        for (int h = lane; h < Hsz; h += 32) p += su[h] * w[h];
#pragma unroll
        for (int o = 16; o > 0; o >>= 1) p += __shfl_xor_sync(0xffffffffu, p, o);
        if (lane == 0) sc[d] = p;
    }
    __syncthreads();
    if (tid == 0) {
        float mx = -1e30f;
        for (int d = 0; d < NDAYS; d++) mx = fmaxf(mx, sc[d]);
        float e[NDAYS], s = 0.f;
        for (int d = 0; d < NDAYS; d++) { e[d] = expf(sc[d] - mx); s += e[d]; }
        for (int d = 0; d < NDAYS; d++) aw[d] = e[d] / s;
    }
    __syncthreads();
    for (int h = tid; h < Hsz; h += 128) {
        float c = 0.f;
#pragma unroll
        for (int d = 0; d < NDAYS; d++)
            c += aw[d] * g_week[((long)b * NDAYS + d) * Hsz + h];
        g_cc[(long)b * 2 * Hsz + Hsz + h] = c;
        g_cc[(long)b * 2 * Hsz + h] = hnew[b * Hsz + h];
    }
}

// ---------------- in-place log_softmax over V ----------------
__global__ void log_softmax_kernel(float* __restrict__ out, int t)
{
    __shared__ float sred[8];
    int b = blockIdx.x, tid = threadIdx.x;  // 256 threads
    float* row = out + ((long)b * Tsz + t) * Vsz;
    float mx = -1e30f;
    for (int i = tid; i < Vsz; i += 256) mx = fmaxf(mx, row[i]);
#pragma unroll
    for (int o = 16; o > 0; o >>= 1) mx = fmaxf(mx, __shfl_xor_sync(0xffffffffu, mx, o));
    if ((tid & 31) == 0) sred[tid >> 5] = mx;
    __syncthreads();
    if (tid == 0) {
        float m = sred[0];
        for (int i = 1; i < 8; i++) m = fmaxf(m, sred[i]);
        sred[0] = m;
    }
    __syncthreads();
    mx = sred[0];
    __syncthreads();
    float s = 0.f;
    for (int i = tid; i < Vsz; i += 256) s += expf(row[i] - mx);
#pragma unroll
    for (int o = 16; o > 0; o >>= 1) s += __shfl_xor_sync(0xffffffffu, s, o);
    if ((tid & 31) == 0) sred[tid >> 5] = s;
    __syncthreads();
    if (tid == 0) {
        float ss = 0.f;
        for (int i = 0; i < 8; i++) ss += sred[i];
        sred[0] = mx + logf(ss);
    }
    __syncthreads();
    float lse = sred[0];
    for (int i = tid; i < Vsz; i += 256) row[i] -= lse;
}

// ---------------- last_in tail output ----------------
__global__ void write_lastin_kernel(const int* __restrict__ label,
                                    float* __restrict__ out)
{
    int b = blockIdx.x * blockDim.x + threadIdx.x;
    if (b < Bsz)
        out[(long)Bsz * Tsz * Vsz + b] = (float)label[b * (Tsz + 1) + (Tsz - 1)];
}

// ---------------- host orchestration ----------------
static void launch_gemm(const float* A, const float* Bm, float* C,
                        int M, int N, int K, int transB, const float* bias,
                        int doTanh, const int* gidx, int ldc)
{
    dim3 grid((N + 63) / 64, (M + 63) / 64);
    sgemm64<<<grid, 128>>>(A, Bm, C, M, N, K, transB, bias, doTanh, gidx, ldc);
}

extern "C" void kernel_launch(void* const* d_in, const int* in_sizes, int n_in,
                              void* d_out, int out_size)
{
    const float* enc_h   = (const float*)d_in[0];
    const float* enc_o   = (const float*)d_in[1];
    const int*   label   = (const int*)d_in[2];
    const int*   numpair = (const int*)d_in[3];
    const float* emb     = (const float*)d_in[4];
    const float* W_ih    = (const float*)d_in[5];
    const float* W_hh    = (const float*)d_in[6];
    const float* b_ih    = (const float*)d_in[7];
    const float* b_hh    = (const float*)d_in[8];
    const float* Wa      = (const float*)d_in[9];
    const float* wa_W    = (const float*)d_in[10];
    const float* fc_W    = (const float*)d_in[11];
    const float* fc_b    = (const float*)d_in[12];
    float* out = (float*)d_out;

    float *p_h, *p_v, *p_u, *p_gh, *p_GI, *p_cc, *p_proj;
    int* p_idx;
    cudaGetSymbolAddress((void**)&p_h,   g_h);
    cudaGetSymbolAddress((void**)&p_v,   g_v);
    cudaGetSymbolAddress((void**)&p_u,   g_u);
    cudaGetSymbolAddress((void**)&p_gh,  g_gh);
    cudaGetSymbolAddress((void**)&p_GI,  g_GI);
    cudaGetSymbolAddress((void**)&p_cc,  g_cc);
    cudaGetSymbolAddress((void**)&p_proj,g_proj);
    cudaGetSymbolAddress((void**)&p_idx, g_idx);

    // h0 = encoder_hidden[0]
    cudaMemcpyAsync(p_h, enc_h, (size_t)Bsz * Hsz * sizeof(float),
                    cudaMemcpyDeviceToDevice);

    // Precompute all GRU input projections (off the critical path):
    build_idx_kernel<<<(Tsz * Bsz + 255) / 256, 256>>>(label);
    launch_gemm(emb, W_ih, p_GI, Tsz * Bsz, H3, Esz, 1, b_ih, 0, p_idx, H3);

    for (int t = 0; t < Tsz; t++) {
        float* hc = p_h + (size_t)(t & 1) * Bsz * Hsz;
        float* hn = p_h + (size_t)((t + 1) & 1) * Bsz * Hsz;

        // v = h @ Wa   (replaces the entire energy_day tensor)
        launch_gemm(hc, Wa, p_v, Bsz, Hsz, Hsz, 0, nullptr, 0, nullptr, Hsz);
        day_attn_kernel<<<Bsz * NDAYS, 256>>>(enc_o, numpair);

        // gh = h @ W_hh^T + b_hh, then gates
        launch_gemm(hc, W_hh, p_gh, Bsz, H3, Hsz, 1, b_hh, 0, nullptr, H3);
        gru_gates_kernel<<<(Bsz * Hsz + 255) / 256, 256>>>(hc, hn, t);

        // u = h_new @ Wa ; week attention + concat
        launch_gemm(hn, Wa, p_u, Bsz, Hsz, Hsz, 0, nullptr, 0, nullptr, Hsz);
        week_attn_kernel<<<Bsz, 128>>>(hn);

        // proj = tanh(cc @ wa_W^T)
        launch_gemm(p_cc, wa_W, p_proj, Bsz, Hsz, 2 * Hsz, 1, nullptr, 1,
                    nullptr, Hsz);

        // logits -> out[:, t, :], then in-place log_softmax
        launch_gemm(p_proj, fc_W, out + (size_t)t * Vsz, Bsz, Vsz, Hsz, 1,
                    fc_b, 0, nullptr, Tsz * Vsz);
        log_softmax_kernel<<<Bsz, 256>>>(out, t);
    }

    if (out_size >= Bsz * Tsz * Vsz + Bsz)
        write_lastin_kernel<<<2, 256>>>(label, out);
}

// round 4
// speedup vs baseline: 2.0535x; 2.0535x over previous
#include <cuda_runtime.h>
#include <cuda_bf16.h>

#define Bsz 512
#define Ssz 140
#define Hsz 512
#define Esz 256
#define Vsz 1000
#define Tsz 21
#define NDAYS 7
#define DLEN 20
#define H3 (3*Hsz)
#define SOS 2
#define NB 2048   // width of [Wa | W_hh^T]

// ---------------- device scratch (allocation-free) ----------------
__device__ float g_h[2*Bsz*Hsz];            // double-buffered hidden state
__device__ float g_vgh[Bsz*NB];             // [v | gh] per batch row
__device__ float g_u[Bsz*Hsz];              // h_new @ Wa
__device__ float g_EW[Vsz*H3];              // emb @ W_ih^T + b_ih  (6 MB)
__device__ float g_BigB[Hsz*NB];            // [Wa | W_hh^T]  (4 MB)
__device__ float g_P[2*Bsz*Hsz];            // split-K partials
__device__ int   g_idx[Tsz*Bsz];            // embedding row per (t,b)
__device__ float g_week[Bsz*NDAYS*Hsz];     // day contexts
__device__ float g_cc[Bsz*2*Hsz];           // [h_new, ctx]
__device__ float g_proj[Bsz*Hsz];           // tanh(cc @ wa_W^T)
__device__ __nv_bfloat16 g_encbf[(size_t)Bsz*Ssz*Hsz];  // 73.4 MB (L2-resident)

// ---------------- one-time setup kernels ----------------
__global__ void build_idx_kernel(const int* __restrict__ label)
{
    int m = blockIdx.x * blockDim.x + threadIdx.x;
    if (m >= Tsz * Bsz) return;
    int t = m / Bsz, b = m % Bsz;
    g_idx[m] = (t == 0) ? SOS : label[b * (Tsz + 1) + (t - 1)];
}

__global__ void build_bigB_kernel(const float* __restrict__ Wa,
                                  const float* __restrict__ W_hh)
{
    int i = blockIdx.x * blockDim.x + threadIdx.x;
    if (i >= Hsz * NB) return;
    int k = i >> 11, n = i & (NB - 1);
    g_BigB[i] = (n < Hsz) ? Wa[k * Hsz + n]
                          : W_hh[(size_t)(n - Hsz) * Hsz + k];
}

__global__ void conv_bf16_kernel(const float* __restrict__ enc)
{
    size_t i = (size_t)blockIdx.x * blockDim.x + threadIdx.x; // one bf16x2
    if (i >= ((size_t)Bsz * Ssz * Hsz) / 2) return;
    float2 f = *(const float2*)(enc + i * 2);
    ((__nv_bfloat162*)g_encbf)[i] = __floats2bfloat162_rn(f.x, f.y);
}

// ---------------- fp32 GEMM: 64x64x16 tile, 256 thr, double-buffered ----------------
// transB=1: B is [N,K] row-major (C = A*B^T); transB=0: B is [K,N] row-major.
// gridDim.z>1: split-K; block z handles K-slice z, writes C + z*splitStride.
__global__ __launch_bounds__(256)
void sgemm(const float* __restrict__ A, const float* __restrict__ Bm,
           float* __restrict__ C, int M, int N, int K, int transB,
           const float* __restrict__ bias, int ldc, size_t splitStride)
{
    __shared__ float As[2][16][64];
    __shared__ float Bs[2][16][64];
    int tid = threadIdx.x;
    int bm = blockIdx.y * 64, bn = blockIdx.x * 64;
    int Kh = K / gridDim.z;
    int kbase = blockIdx.z * Kh;
    C += (size_t)blockIdx.z * splitStride;

    int tx = tid & 15, ty = tid >> 4;
    int arow = tid >> 2, akc = (tid & 3) << 2;   // A loader: row, k
    int bkr  = tid >> 4, bnc = (tid & 15) << 2;  // B non-trans loader
    int brow = tid >> 2, bkc = (tid & 3) << 2;   // B trans loader

    const float4 zero4 = make_float4(0.f, 0.f, 0.f, 0.f);
    float4 aR, bR;

    // prologue: tile 0 -> buffer 0
    aR = (bm + arow < M) ? *(const float4*)(A + (size_t)(bm + arow) * K + kbase + akc) : zero4;
    if (transB)
        bR = (bn + brow < N) ? *(const float4*)(Bm + (size_t)(bn + brow) * K + kbase + bkc) : zero4;
    else
        bR = (bn + bnc < N) ? *(const float4*)(Bm + (size_t)(kbase + bkr) * N + bn + bnc) : zero4;
    As[0][akc + 0][arow] = aR.x; As[0][akc + 1][arow] = aR.y;
    As[0][akc + 2][arow] = aR.z; As[0][akc + 3][arow] = aR.w;
    if (transB) {
        Bs[0][bkc + 0][brow] = bR.x; Bs[0][bkc + 1][brow] = bR.y;
        Bs[0][bkc + 2][brow] = bR.z; Bs[0][bkc + 3][brow] = bR.w;
    } else {
        *(float4*)&Bs[0][bkr][bnc] = bR;
    }
    __syncthreads();

    float acc[4][4];
#pragma unroll
    for (int i = 0; i < 4; i++)
#pragma unroll
        for (int j = 0; j < 4; j++) acc[i][j] = 0.f;

    int nt = Kh >> 4;
    for (int kt = 0; kt < nt; kt++) {
        int cur = kt & 1;
        bool more = (kt + 1 < nt);
        if (more) {
            int kp = kbase + ((kt + 1) << 4);
            aR = (bm + arow < M) ? *(const float4*)(A + (size_t)(bm + arow) * K + kp + akc) : zero4;
            if (transB)
                bR = (bn + brow < N) ? *(const float4*)(Bm + (size_t)(bn + brow) * K + kp + bkc) : zero4;
            else
                bR = (bn + bnc < N) ? *(const float4*)(Bm + (size_t)(kp + bkr) * N + bn + bnc) : zero4;
        }
#pragma unroll
        for (int kk = 0; kk < 16; kk++) {
            float4 av = *(const float4*)&As[cur][kk][ty << 2];
            float4 bv = *(const float4*)&Bs[cur][kk][tx << 2];
            float a_[4] = {av.x, av.y, av.z, av.w};
            float b_[4] = {bv.x, bv.y, bv.z, bv.w};
#pragma unroll
            for (int i = 0; i < 4; i++)
#pragma unroll
                for (int j = 0; j < 4; j++)
                    acc[i][j] += a_[i] * b_[j];
        }
        if (more) {
            int nx = cur ^ 1;
            As[nx][akc + 0][arow] = aR.x; As[nx][akc + 1][arow] = aR.y;
            As[nx][akc + 2][arow] = aR.z; As[nx][akc + 3][arow] = aR.w;
            if (transB) {
                Bs[nx][bkc + 0][brow] = bR.x; Bs[nx][bkc + 1][brow] = bR.y;
                Bs[nx][bkc + 2][brow] = bR.z; Bs[nx][bkc + 3][brow] = bR.w;
            } else {
                *(float4*)&Bs[nx][bkr][bnc] = bR;
            }
        }
        __syncthreads();
    }

#pragma unroll
    for (int i = 0; i < 4; i++) {
        int m = bm + (ty << 2) + i;
        if (m < M) {
#pragma unroll
            for (int j = 0; j < 4; j++) {
                int n = bn + (tx << 2) + j;
                if (n < N) {
                    float v = acc[i][j];
                    if (bias) v += bias[n];
                    C[(size_t)m * ldc + n] = v;
                }
            }
        }
    }
}

// ---------------- split-K combine: dst = (tanh?)(P0 + P1) ----------------
__global__ void combine_kernel(float* __restrict__ dst, const float* __restrict__ P,
                               int n, int doTanh)
{
    int i = blockIdx.x * blockDim.x + threadIdx.x;
    if (i >= n) return;
    float v = P[i] + P[i + n];
    dst[i] = doTanh ? tanhf(v) : v;
}

// ---------------- day-level attention (bf16 enc, L2-resident) ----------------
__global__ __launch_bounds__(256)
void day_attn_kernel(const int* __restrict__ numpairs)
{
    __shared__ float sv[Hsz];
    __shared__ __align__(16) __nv_bfloat16 tile[DLEN * Hsz]; // 20 KB
    __shared__ float ssc[DLEN];
    __shared__ float swt[DLEN];
    int b = blockIdx.x / NDAYS, d = blockIdx.x % NDAYS;
    int tid = threadIdx.x;

    for (int i = tid; i < Hsz; i += 256) sv[i] = g_vgh[(size_t)b * NB + i];
    const uint4* ep = (const uint4*)(g_encbf + ((size_t)b * Ssz + d * DLEN) * Hsz);
    uint4* tp = (uint4*)tile;
#pragma unroll
    for (int i = tid; i < DLEN * Hsz * 2 / 16; i += 256) tp[i] = ep[i];
    __syncthreads();

    int warp = tid >> 5, lane = tid & 31;
    const __nv_bfloat162* t2 = (const __nv_bfloat162*)tile;
    for (int s = warp; s < DLEN; s += 8) {
        float p = 0.f;
        for (int hp = lane; hp < Hsz / 2; hp += 32) {
            float2 cv = __bfloat1622float2(t2[s * (Hsz / 2) + hp]);
            p += sv[2 * hp] * cv.x + sv[2 * hp + 1] * cv.y;
        }
#pragma unroll
        for (int o = 16; o > 0; o >>= 1) p += __shfl_xor_sync(0xffffffffu, p, o);
        if (lane == 0) ssc[s] = p;
    }
    __syncthreads();
    if (tid < 32) {
        float val = -1e30f;
        if (tid < DLEN)
            val = (numpairs[b * Ssz + d * DLEN + tid] != 0) ? ssc[tid] : -1e9f;
        float mx = val;
#pragma unroll
        for (int o = 16; o > 0; o >>= 1) mx = fmaxf(mx, __shfl_xor_sync(0xffffffffu, mx, o));
        float e = (tid < DLEN) ? expf(val - mx) : 0.f;
        float sm = e;
#pragma unroll
        for (int o = 16; o > 0; o >>= 1) sm += __shfl_xor_sync(0xffffffffu, sm, o);
        if (tid < DLEN) swt[tid] = e / sm;
    }
    __syncthreads();
    {
        int hp = tid;   // 256 threads x 2 h = 512
        float2 a = make_float2(0.f, 0.f);
#pragma unroll
        for (int s = 0; s < DLEN; s++) {
            float2 cv = __bfloat1622float2(t2[s * (Hsz / 2) + hp]);
            a.x += swt[s] * cv.x;
            a.y += swt[s] * cv.y;
        }
        float* wk = g_week + ((size_t)b * NDAYS + d) * Hsz;
        wk[2 * hp] = a.x;
        wk[2 * hp + 1] = a.y;
    }
}

// ---------------- GRU gates (gathers EW[label], gh from g_vgh) ----------------
__global__ void gru_gates_kernel(const float* __restrict__ hcur,
                                 float* __restrict__ hnew,
                                 const float* __restrict__ b_hh, int t)
{
    int i = blockIdx.x * blockDim.x + threadIdx.x;
    if (i >= Bsz * Hsz) return;
    int b = i >> 9, j = i & 511;
    const float* gi = g_EW + (size_t)g_idx[t * Bsz + b] * H3;
    const float* gh = g_vgh + (size_t)b * NB + Hsz;
    float ir = gi[j], iz = gi[j + Hsz], inn = gi[j + 2 * Hsz];
    float hr = gh[j] + b_hh[j];
    float hz = gh[j + Hsz] + b_hh[j + Hsz];
    float hn_ = gh[j + 2 * Hsz] + b_hh[j + 2 * Hsz];
    float r = 1.f / (1.f + expf(-(ir + hr)));
    float z = 1.f / (1.f + expf(-(iz + hz)));
    float n = tanhf(inn + r * hn_);
    hnew[i] = (1.f - z) * n + z * hcur[i];
}

// ---------------- week-level attention + concat ----------------
__global__ void week_attn_kernel(const float* __restrict__ hnew)
{
    __shared__ float su[Hsz];
    __shared__ float sc[8];
    __shared__ float aw[8];
    int b = blockIdx.x, tid = threadIdx.x;  // 128 threads
    for (int i = tid; i < Hsz; i += 128) su[i] = g_u[b * Hsz + i];
    __syncthreads();
    int warp = tid >> 5, lane = tid & 31;
    for (int d = warp; d < NDAYS; d += 4) {
        const float* w = g_week + ((size_t)b * NDAYS + d) * Hsz;
        float p = 0.f;
        for (int h = lane; h < Hsz; h += 32) p += su[h] * w[h];
#pragma unroll
        for (int o = 16; o > 0; o >>= 1) p += __shfl_xor_sync(0xffffffffu, p, o);
        if (lane == 0) sc[d] = p;
    }
    __syncthreads();
    if (tid == 0) {
        float mx = -1e30f;
        for (int d = 0; d < NDAYS; d++) mx = fmaxf(mx, sc[d]);
        float e[NDAYS], s = 0.f;
        for (int d = 0; d < NDAYS; d++) { e[d] = expf(sc[d] - mx); s += e[d]; }
        for (int d = 0; d < NDAYS; d++) aw[d] = e[d] / s;
    }
    __syncthreads();
    for (int h = tid; h < Hsz; h += 128) {
        float c = 0.f;
#pragma unroll
        for (int d = 0; d < NDAYS; d++)
            c += aw[d] * g_week[((size_t)b * NDAYS + d) * Hsz + h];
        g_cc[(size_t)b * 2 * Hsz + Hsz + h] = c;
        g_cc[(size_t)b * 2 * Hsz + h] = hnew[b * Hsz + h];
    }
}

// ---------------- in-place log_softmax over V ----------------
__global__ void log_softmax_kernel(float* __restrict__ out, int t)
{
    __shared__ float sred[8];
    int b = blockIdx.x, tid = threadIdx.x;  // 256 threads
    float* row = out + ((size_t)b * Tsz + t) * Vsz;
    float mx = -1e30f;
    for (int i = tid; i < Vsz; i += 256) mx = fmaxf(mx, row[i]);
#pragma unroll
    for (int o = 16; o > 0; o >>= 1) mx = fmaxf(mx, __shfl_xor_sync(0xffffffffu, mx, o));
    if ((tid & 31) == 0) sred[tid >> 5] = mx;
    __syncthreads();
    if (tid == 0) {
        float m = sred[0];
        for (int i = 1; i < 8; i++) m = fmaxf(m, sred[i]);
        sred[0] = m;
    }
    __syncthreads();
    mx = sred[0];
    __syncthreads();
    float s = 0.f;
    for (int i = tid; i < Vsz; i += 256) s += expf(row[i] - mx);
#pragma unroll
    for (int o = 16; o > 0; o >>= 1) s += __shfl_xor_sync(0xffffffffu, s, o);
    if ((tid & 31) == 0) sred[tid >> 5] = s;
    __syncthreads();
    if (tid == 0) {
        float ss = 0.f;
        for (int i = 0; i < 8; i++) ss += sred[i];
        sred[0] = mx + logf(ss);
    }
    __syncthreads();
    float lse = sred[0];
    for (int i = tid; i < Vsz; i += 256) row[i] -= lse;
}

__global__ void write_lastin_kernel(const int* __restrict__ label,
                                    float* __restrict__ out)
{
    int b = blockIdx.x * blockDim.x + threadIdx.x;
    if (b < Bsz)
        out[(size_t)Bsz * Tsz * Vsz + b] = (float)label[b * (Tsz + 1) + (Tsz - 1)];
}

// ---------------- host orchestration ----------------
static void launch_gemm(const float* A, const float* Bm, float* C,
                        int M, int N, int K, int transB, const float* bias,
                        int ldc, int splitZ, size_t splitStride)
{
    dim3 grid((N + 63) / 64, (M + 63) / 64, splitZ);
    sgemm<<<grid, 256>>>(A, Bm, C, M, N, K, transB, bias, ldc, splitStride);
}

extern "C" void kernel_launch(void* const* d_in, const int* in_sizes, int n_in,
                              void* d_out, int out_size)
{
    const float* enc_h   = (const float*)d_in[0];
    const float* enc_o   = (const float*)d_in[1];
    const int*   label   = (const int*)d_in[2];
    const int*   numpair = (const int*)d_in[3];
    const float* emb     = (const float*)d_in[4];
    const float* W_ih    = (const float*)d_in[5];
    const float* W_hh    = (const float*)d_in[6];
    const float* b_ih    = (const float*)d_in[7];
    const float* b_hh    = (const float*)d_in[8];
    const float* Wa      = (const float*)d_in[9];
    const float* wa_W    = (const float*)d_in[10];
    const float* fc_W    = (const float*)d_in[11];
    const float* fc_b    = (const float*)d_in[12];
    float* out = (float*)d_out;

    float *p_h, *p_vgh, *p_u, *p_EW, *p_BigB, *p_P, *p_cc, *p_proj;
    cudaGetSymbolAddress((void**)&p_h,    g_h);
    cudaGetSymbolAddress((void**)&p_vgh,  g_vgh);
    cudaGetSymbolAddress((void**)&p_u,    g_u);
    cudaGetSymbolAddress((void**)&p_EW,   g_EW);
    cudaGetSymbolAddress((void**)&p_BigB, g_BigB);
    cudaGetSymbolAddress((void**)&p_P,    g_P);
    cudaGetSymbolAddress((void**)&p_cc,   g_cc);
    cudaGetSymbolAddress((void**)&p_proj, g_proj);

    // h0 = encoder_hidden[0]
    cudaMemcpyAsync(p_h, enc_h, (size_t)Bsz * Hsz * sizeof(float),
                    cudaMemcpyDeviceToDevice);

    // one-time setup
    build_idx_kernel<<<(Tsz * Bsz + 255) / 256, 256>>>(label);
    build_bigB_kernel<<<(Hsz * NB + 255) / 256, 256>>>(Wa, W_hh);
    conv_bf16_kernel<<<(int)(((size_t)Bsz * Ssz * Hsz / 2 + 255) / 256), 256>>>(enc_o);
    // EW = emb @ W_ih^T + b_ih   [1000 x 1536]
    launch_gemm(emb, W_ih, p_EW, Vsz, H3, Esz, 1, b_ih, H3, 1, 0);

    const size_t SSTR = (size_t)Bsz * Hsz;

    for (int t = 0; t < Tsz; t++) {
        float* hc = p_h + (size_t)(t & 1) * Bsz * Hsz;
        float* hn = p_h + (size_t)((t + 1) & 1) * Bsz * Hsz;

        // [v | gh] = h @ [Wa | W_hh^T]   (N=2048, 128 CTAs)
        launch_gemm(hc, p_BigB, p_vgh, Bsz, NB, Hsz, 0, nullptr, NB, 1, 0);

        day_attn_kernel<<<Bsz * NDAYS, 256>>>(numpair);
        gru_gates_kernel<<<(Bsz * Hsz + 255) / 256, 256>>>(hc, hn, b_hh, t);

        // u = h_new @ Wa  (split-K 2)
        launch_gemm(hn, Wa, p_P, Bsz, Hsz, Hsz, 0, nullptr, Hsz, 2, SSTR);
        combine_kernel<<<(Bsz * Hsz + 255) / 256, 256>>>(p_u, p_P, Bsz * Hsz, 0);

        week_attn_kernel<<<Bsz, 128>>>(hn);

        // proj = tanh(cc @ wa_W^T)  (K=1024, split-K 2)
        launch_gemm(p_cc, wa_W, p_P, Bsz, Hsz, 2 * Hsz, 1, nullptr, Hsz, 2, SSTR);
        combine_kernel<<<(Bsz * Hsz + 255) / 256, 256>>>(p_proj, p_P, Bsz * Hsz, 1);

        // logits -> out[:, t, :]
        launch_gemm(p_proj, fc_W, out + (size_t)t * Vsz, Bsz, Vsz, Hsz, 1,
                    fc_b, Tsz * Vsz, 1, 0);
        log_softmax_kernel<<<Bsz, 256>>>(out, t);
    }

    if (out_size >= Bsz * Tsz * Vsz + Bsz)
        write_lastin_kernel<<<2, 256>>>(label, out);
}

// round 8
// speedup vs baseline: 2.5958x; 1.2641x over previous
#include <cuda_runtime.h>
#include <cuda_bf16.h>

#define Bsz 512
#define Ssz 140
#define Hsz 512
#define Esz 256
#define Vsz 1000
#define Tsz 21
#define NDAYS 7
#define DLEN 20
#define H3 (3*Hsz)
#define SOS 2
#define NB 2048   // width of [Wa | W_hh^T]
#define SMP 72    // smem row stride (conflict-free mma fragment loads)

// ---------------- device scratch (allocation-free) ----------------
__device__ float g_h[2*Bsz*Hsz];            // double-buffered hidden state
__device__ float g_vgh[Bsz*NB];             // [v | gh] per batch row
__device__ float g_EW[Vsz*H3];              // emb @ W_ih^T + b_ih
__device__ float g_BigB[Hsz*NB];            // [Wa | W_hh^T]
__device__ float g_P[2*Bsz*Hsz];            // split-K partials
__device__ int   g_idx[Tsz*Bsz];            // embedding row per (t,b)
__device__ float g_week[Bsz*NDAYS*Hsz];     // day contexts
__device__ float g_cc[Bsz*2*Hsz];           // [h_new, ctx]
__device__ float g_proj[Bsz*Hsz];           // tanh(cc @ wa_W^T)
__device__ __nv_bfloat16 g_encbf[(size_t)Bsz*Ssz*Hsz];  // 73.4 MB (L2-resident)

// ---------------- tf32 helpers ----------------
__device__ __forceinline__ float tf32r(float x)
{
    asm("cvt.rna.tf32.f32 %0, %0;" : "+f"(x));
    return x;
}

__device__ __forceinline__ void mma8(float (&d)[4], const unsigned (&a)[4],
                                     unsigned b0, unsigned b1)
{
    asm("mma.sync.aligned.m16n8k8.row.col.f32.tf32.tf32.f32 "
        "{%0,%1,%2,%3},{%4,%5,%6,%7},{%8,%9},{%0,%1,%2,%3};"
        : "+f"(d[0]), "+f"(d[1]), "+f"(d[2]), "+f"(d[3])
        : "r"(a[0]), "r"(a[1]), "r"(a[2]), "r"(a[3]), "r"(b0), "r"(b1));
}

// ---------------- one-time setup kernels ----------------
__global__ void build_idx_kernel(const int* __restrict__ label)
{
    int m = blockIdx.x * blockDim.x + threadIdx.x;
    if (m >= Tsz * Bsz) return;
    int t = m / Bsz, b = m % Bsz;
    g_idx[m] = (t == 0) ? SOS : label[b * (Tsz + 1) + (t - 1)];
}

__global__ void build_bigB_kernel(const float* __restrict__ Wa,
                                  const float* __restrict__ W_hh)
{
    int i = blockIdx.x * blockDim.x + threadIdx.x;
    if (i >= Hsz * NB) return;
    int k = i >> 11, n = i & (NB - 1);
    g_BigB[i] = (n < Hsz) ? Wa[k * Hsz + n]
                          : W_hh[(size_t)(n - Hsz) * Hsz + k];
}

__global__ void conv_bf16_kernel(const float* __restrict__ enc)
{
    size_t i = (size_t)blockIdx.x * blockDim.x + threadIdx.x;
    if (i >= ((size_t)Bsz * Ssz * Hsz) / 2) return;
    float2 f = *(const float2*)(enc + i * 2);
    ((__nv_bfloat162*)g_encbf)[i] = __floats2bfloat162_rn(f.x, f.y);
}

// ---------------- tf32 tensor-core GEMM ----------------
// 64x64 tile, BK=16, 256 thr = 8 warps in a 2(m) x 4(n) grid; each warp
// owns a 32x16 sub-tile (mi in {0,1} m16 halves, ni in {0,1} n8 halves).
// transB=1: B is [N,K] row-major (C = A*B^T); transB=0: B is [K,N] row-major.
// gridDim.z>1: split-K; block z handles K-slice z, writes C + z*splitStride.
__global__ __launch_bounds__(256)
void tgemm(const float* __restrict__ A, const float* __restrict__ Bm,
           float* __restrict__ C, int M, int N, int K, int transB,
           const float* __restrict__ bias, int ldc, size_t splitStride)
{
    __shared__ float As[2][16][SMP];
    __shared__ float Bs[2][16][SMP];
    int tid = threadIdx.x;
    int bm = blockIdx.y * 64, bn = blockIdx.x * 64;
    int Kh = K / gridDim.z;
    int kbase = blockIdx.z * Kh;
    C += (size_t)blockIdx.z * splitStride;

    int lane = tid & 31, warp = tid >> 5;          // warp 0..7
    int wm = (warp >> 2) * 32, wn = (warp & 3) * 16;  // 2x4 warp grid
    int gr = lane >> 2, tg = lane & 3;

    int arow = tid >> 2, akc = (tid & 3) << 2;   // A loader
    int bkr  = tid >> 4, bnc = (tid & 15) << 2;  // B non-trans loader
    int brow = tid >> 2, bkc = (tid & 3) << 2;   // B trans loader

    const float4 zero4 = make_float4(0.f, 0.f, 0.f, 0.f);
    float4 aR, bR;

    // prologue: tile 0 -> buffer 0
    aR = (bm + arow < M) ? *(const float4*)(A + (size_t)(bm + arow) * K + kbase + akc) : zero4;
    if (transB)
        bR = (bn + brow < N) ? *(const float4*)(Bm + (size_t)(bn + brow) * K + kbase + bkc) : zero4;
    else
        bR = (bn + bnc < N) ? *(const float4*)(Bm + (size_t)(kbase + bkr) * N + bn + bnc) : zero4;
    As[0][akc + 0][arow] = tf32r(aR.x); As[0][akc + 1][arow] = tf32r(aR.y);
    As[0][akc + 2][arow] = tf32r(aR.z); As[0][akc + 3][arow] = tf32r(aR.w);
    if (transB) {
        Bs[0][bkc + 0][brow] = tf32r(bR.x); Bs[0][bkc + 1][brow] = tf32r(bR.y);
        Bs[0][bkc + 2][brow] = tf32r(bR.z); Bs[0][bkc + 3][brow] = tf32r(bR.w);
    } else {
        Bs[0][bkr][bnc + 0] = tf32r(bR.x); Bs[0][bkr][bnc + 1] = tf32r(bR.y);
        Bs[0][bkr][bnc + 2] = tf32r(bR.z); Bs[0][bkr][bnc + 3] = tf32r(bR.w);
    }
    __syncthreads();

    float acc[2][2][4];
#pragma unroll
    for (int mi = 0; mi < 2; mi++)
#pragma unroll
        for (int ni = 0; ni < 2; ni++)
#pragma unroll
            for (int q = 0; q < 4; q++) acc[mi][ni][q] = 0.f;

    int nt = Kh >> 4;
    for (int kt = 0; kt < nt; kt++) {
        int cur = kt & 1;
        bool more = (kt + 1 < nt);
        if (more) {
            int kp = kbase + ((kt + 1) << 4);
            aR = (bm + arow < M) ? *(const float4*)(A + (size_t)(bm + arow) * K + kp + akc) : zero4;
            if (transB)
                bR = (bn + brow < N) ? *(const float4*)(Bm + (size_t)(bn + brow) * K + kp + bkc) : zero4;
            else
                bR = (bn + bnc < N) ? *(const float4*)(Bm + (size_t)(kp + bkr) * N + bn + bnc) : zero4;
        }
#pragma unroll
        for (int ks = 0; ks < 2; ks++) {
            int k0 = ks << 3;
            unsigned afr[2][4];
#pragma unroll
            for (int mi = 0; mi < 2; mi++) {
                int rm = wm + mi * 16 + gr;
                afr[mi][0] = __float_as_uint(As[cur][k0 + tg][rm]);
                afr[mi][1] = __float_as_uint(As[cur][k0 + tg][rm + 8]);
                afr[mi][2] = __float_as_uint(As[cur][k0 + tg + 4][rm]);
                afr[mi][3] = __float_as_uint(As[cur][k0 + tg + 4][rm + 8]);
            }
#pragma unroll
            for (int ni = 0; ni < 2; ni++) {
                int cn = wn + ni * 8 + gr;
                unsigned b0 = __float_as_uint(Bs[cur][k0 + tg][cn]);
                unsigned b1 = __float_as_uint(Bs[cur][k0 + tg + 4][cn]);
                mma8(acc[0][ni], afr[0], b0, b1);
                mma8(acc[1][ni], afr[1], b0, b1);
            }
        }
        if (more) {
            int nx = cur ^ 1;
            As[nx][akc + 0][arow] = tf32r(aR.x); As[nx][akc + 1][arow] = tf32r(aR.y);
            As[nx][akc + 2][arow] = tf32r(aR.z); As[nx][akc + 3][arow] = tf32r(aR.w);
            if (transB) {
                Bs[nx][bkc + 0][brow] = tf32r(bR.x); Bs[nx][bkc + 1][brow] = tf32r(bR.y);
                Bs[nx][bkc + 2][brow] = tf32r(bR.z); Bs[nx][bkc + 3][brow] = tf32r(bR.w);
            } else {
                Bs[nx][bkr][bnc + 0] = tf32r(bR.x); Bs[nx][bkr][bnc + 1] = tf32r(bR.y);
                Bs[nx][bkr][bnc + 2] = tf32r(bR.z); Bs[nx][bkr][bnc + 3] = tf32r(bR.w);
            }
        }
        __syncthreads();
    }

    // epilogue: mma C-fragment layout -> global
#pragma unroll
    for (int mi = 0; mi < 2; mi++) {
        int r0 = bm + wm + mi * 16 + gr;
        int r1 = r0 + 8;
#pragma unroll
        for (int ni = 0; ni < 2; ni++) {
            int c0 = bn + wn + ni * 8 + 2 * tg;
            float bb0 = bias ? bias[min(c0, N - 1)] : 0.f;
            float bb1 = bias ? bias[min(c0 + 1, N - 1)] : 0.f;
            if (r0 < M) {
                if (c0 < N)     C[(size_t)r0 * ldc + c0]     = acc[mi][ni][0] + bb0;
                if (c0 + 1 < N) C[(size_t)r0 * ldc + c0 + 1] = acc[mi][ni][1] + bb1;
            }
            if (r1 < M) {
                if (c0 < N)     C[(size_t)r1 * ldc + c0]     = acc[mi][ni][2] + bb0;
                if (c0 + 1 < N) C[(size_t)r1 * ldc + c0 + 1] = acc[mi][ni][3] + bb1;
            }
        }
    }
}

// ---------------- split-K combine (tanh) for proj ----------------
__global__ void combine_kernel(float* __restrict__ dst, const float* __restrict__ P,
                               int n, int doTanh)
{
    int i = blockIdx.x * blockDim.x + threadIdx.x;
    if (i >= n) return;
    float v = P[i] + P[i + n];
    dst[i] = doTanh ? tanhf(v) : v;
}

// ---------------- day-level attention (bf16 enc, L2-resident) ----------------
__global__ __launch_bounds__(256)
void day_attn_kernel(const int* __restrict__ numpairs)
{
    __shared__ float sv[Hsz];
    __shared__ __align__(16) __nv_bfloat16 tile[DLEN * Hsz];
    __shared__ float ssc[DLEN];
    __shared__ float swt[DLEN];
    int b = blockIdx.x / NDAYS, d = blockIdx.x % NDAYS;
    int tid = threadIdx.x;

    for (int i = tid; i < Hsz; i += 256) sv[i] = g_vgh[(size_t)b * NB + i];
    const uint4* ep = (const uint4*)(g_encbf + ((size_t)b * Ssz + d * DLEN) * Hsz);
    uint4* tp = (uint4*)tile;
#pragma unroll
    for (int i = tid; i < DLEN * Hsz * 2 / 16; i += 256) tp[i] = ep[i];
    __syncthreads();

    int warp = tid >> 5, lane = tid & 31;
    const __nv_bfloat162* t2 = (const __nv_bfloat162*)tile;
    for (int s = warp; s < DLEN; s += 8) {
        float p = 0.f;
        for (int hp = lane; hp < Hsz / 2; hp += 32) {
            float2 cv = __bfloat1622float2(t2[s * (Hsz / 2) + hp]);
            p += sv[2 * hp] * cv.x + sv[2 * hp + 1] * cv.y;
        }
#pragma unroll
        for (int o = 16; o > 0; o >>= 1) p += __shfl_xor_sync(0xffffffffu, p, o);
        if (lane == 0) ssc[s] = p;
    }
    __syncthreads();
    if (tid < 32) {
        float val = -1e30f;
        if (tid < DLEN)
            val = (numpairs[b * Ssz + d * DLEN + tid] != 0) ? ssc[tid] : -1e9f;
        float mx = val;
#pragma unroll
        for (int o = 16; o > 0; o >>= 1) mx = fmaxf(mx, __shfl_xor_sync(0xffffffffu, mx, o));
        float e = (tid < DLEN) ? expf(val - mx) : 0.f;
        float sm = e;
#pragma unroll
        for (int o = 16; o > 0; o >>= 1) sm += __shfl_xor_sync(0xffffffffu, sm, o);
        if (tid < DLEN) swt[tid] = e / sm;
    }
    __syncthreads();
    {
        int hp = tid;
        float2 a = make_float2(0.f, 0.f);
#pragma unroll
        for (int s = 0; s < DLEN; s++) {
            float2 cv = __bfloat1622float2(t2[s * (Hsz / 2) + hp]);
            a.x += swt[s] * cv.x;
            a.y += swt[s] * cv.y;
        }
        float* wk = g_week + ((size_t)b * NDAYS + d) * Hsz;
        wk[2 * hp] = a.x;
        wk[2 * hp + 1] = a.y;
    }
}

// ---------------- GRU gates ----------------
__global__ void gru_gates_kernel(const float* __restrict__ hcur,
                                 float* __restrict__ hnew,
                                 const float* __restrict__ b_hh, int t)
{
    int i = blockIdx.x * blockDim.x + threadIdx.x;
    if (i >= Bsz * Hsz) return;
    int b = i >> 9, j = i & 511;
    const float* gi = g_EW + (size_t)g_idx[t * Bsz + b] * H3;
    const float* gh = g_vgh + (size_t)b * NB + Hsz;
    float ir = gi[j], iz = gi[j + Hsz], inn = gi[j + 2 * Hsz];
    float hr = gh[j] + b_hh[j];
    float hz = gh[j + Hsz] + b_hh[j + Hsz];
    float hn_ = gh[j + 2 * Hsz] + b_hh[j + 2 * Hsz];
    float r = 1.f / (1.f + expf(-(ir + hr)));
    float z = 1.f / (1.f + expf(-(iz + hz)));
    float n = tanhf(inn + r * hn_);
    hnew[i] = (1.f - z) * n + z * hcur[i];
}

// ---------------- week-level attention + concat (u combine fused) ----------------
__global__ void week_attn_kernel(const float* __restrict__ hnew)
{
    __shared__ float su[Hsz];
    __shared__ float sc[8];
    __shared__ float aw[8];
    int b = blockIdx.x, tid = threadIdx.x;  // 128 threads
    const size_t SSTR = (size_t)Bsz * Hsz;
    for (int i = tid; i < Hsz; i += 128)
        su[i] = g_P[(size_t)b * Hsz + i] + g_P[SSTR + (size_t)b * Hsz + i];
    __syncthreads();
    int warp = tid >> 5, lane = tid & 31;
    for (int d = warp; d < NDAYS; d += 4) {
        const float* w = g_week + ((size_t)b * NDAYS + d) * Hsz;
        float p = 0.f;
        for (int h = lane; h < Hsz; h += 32) p += su[h] * w[h];
#pragma unroll
        for (int o = 16; o > 0; o >>= 1) p += __shfl_xor_sync(0xffffffffu, p, o);
        if (lane == 0) sc[d] = p;
    }
    __syncthreads();
    if (tid == 0) {
        float mx = -1e30f;
        for (int d = 0; d < NDAYS; d++) mx = fmaxf(mx, sc[d]);
        float e[NDAYS], s = 0.f;
        for (int d = 0; d < NDAYS; d++) { e[d] = expf(sc[d] - mx); s += e[d]; }
        for (int d = 0; d < NDAYS; d++) aw[d] = e[d] / s;
    }
    __syncthreads();
    for (int h = tid; h < Hsz; h += 128) {
        float c = 0.f;
#pragma unroll
        for (int d = 0; d < NDAYS; d++)
            c += aw[d] * g_week[((size_t)b * NDAYS + d) * Hsz + h];
        g_cc[(size_t)b * 2 * Hsz + Hsz + h] = c;
        g_cc[(size_t)b * 2 * Hsz + h] = hnew[b * Hsz + h];
    }
}

// ---------------- in-place log_softmax over V ----------------
__global__ void log_softmax_kernel(float* __restrict__ out, int t)
{
    __shared__ float sred[8];
    int b = blockIdx.x, tid = threadIdx.x;
    float* row = out + ((size_t)b * Tsz + t) * Vsz;
    float mx = -1e30f;
    for (int i = tid; i < Vsz; i += 256) mx = fmaxf(mx, row[i]);
#pragma unroll
    for (int o = 16; o > 0; o >>= 1) mx = fmaxf(mx, __shfl_xor_sync(0xffffffffu, mx, o));
    if ((tid & 31) == 0) sred[tid >> 5] = mx;
    __syncthreads();
    if (tid == 0) {
        float m = sred[0];
        for (int i = 1; i < 8; i++) m = fmaxf(m, sred[i]);
        sred[0] = m;
    }
    __syncthreads();
    mx = sred[0];
    __syncthreads();
    float s = 0.f;
    for (int i = tid; i < Vsz; i += 256) s += expf(row[i] - mx);
#pragma unroll
    for (int o = 16; o > 0; o >>= 1) s += __shfl_xor_sync(0xffffffffu, s, o);
    if ((tid & 31) == 0) sred[tid >> 5] = s;
    __syncthreads();
    if (tid == 0) {
        float ss = 0.f;
        for (int i = 0; i < 8; i++) ss += sred[i];
        sred[0] = mx + logf(ss);
    }
    __syncthreads();
    float lse = sred[0];
    for (int i = tid; i < Vsz; i += 256) row[i] -= lse;
}

__global__ void write_lastin_kernel(const int* __restrict__ label,
                                    float* __restrict__ out)
{
    int b = blockIdx.x * blockDim.x + threadIdx.x;
    if (b < Bsz)
        out[(size_t)Bsz * Tsz * Vsz + b] = (float)label[b * (Tsz + 1) + (Tsz - 1)];
}

// ---------------- host orchestration ----------------
static void launch_gemm(const float* A, const float* Bm, float* C,
                        int M, int N, int K, int transB, const float* bias,
                        int ldc, int splitZ, size_t splitStride)
{
    dim3 grid((N + 63) / 64, (M + 63) / 64, splitZ);
    tgemm<<<grid, 256>>>(A, Bm, C, M, N, K, transB, bias, ldc, splitStride);
}

extern "C" void kernel_launch(void* const* d_in, const int* in_sizes, int n_in,
                              void* d_out, int out_size)
{
    const float* enc_h   = (const float*)d_in[0];
    const float* enc_o   = (const float*)d_in[1];
    const int*   label   = (const int*)d_in[2];
    const int*   numpair = (const int*)d_in[3];
    const float* emb     = (const float*)d_in[4];
    const float* W_ih    = (const float*)d_in[5];
    const float* W_hh    = (const float*)d_in[6];
    const float* b_ih    = (const float*)d_in[7];
    const float* b_hh    = (const float*)d_in[8];
    const float* Wa      = (const float*)d_in[9];
    const float* wa_W    = (const float*)d_in[10];
    const float* fc_W    = (const float*)d_in[11];
    const float* fc_b    = (const float*)d_in[12];
    float* out = (float*)d_out;

    float *p_h, *p_vgh, *p_EW, *p_BigB, *p_P, *p_cc, *p_proj;
    cudaGetSymbolAddress((void**)&p_h,    g_h);
    cudaGetSymbolAddress((void**)&p_vgh,  g_vgh);
    cudaGetSymbolAddress((void**)&p_EW,   g_EW);
    cudaGetSymbolAddress((void**)&p_BigB, g_BigB);
    cudaGetSymbolAddress((void**)&p_P,    g_P);
    cudaGetSymbolAddress((void**)&p_cc,   g_cc);
    cudaGetSymbolAddress((void**)&p_proj, g_proj);

    // h0 = encoder_hidden[0]
    cudaMemcpyAsync(p_h, enc_h, (size_t)Bsz * Hsz * sizeof(float),
                    cudaMemcpyDeviceToDevice);

    // one-time setup
    build_idx_kernel<<<(Tsz * Bsz + 255) / 256, 256>>>(label);
    build_bigB_kernel<<<(Hsz * NB + 255) / 256, 256>>>(Wa, W_hh);
    conv_bf16_kernel<<<(int)(((size_t)Bsz * Ssz * Hsz / 2 + 255) / 256), 256>>>(enc_o);
    // EW = emb @ W_ih^T + b_ih   [1000 x 1536]
    launch_gemm(emb, W_ih, p_EW, Vsz, H3, Esz, 1, b_ih, H3, 1, 0);

    const size_t SSTR = (size_t)Bsz * Hsz;

    for (int t = 0; t < Tsz; t++) {
        float* hc = p_h + (size_t)(t & 1) * Bsz * Hsz;
        float* hn = p_h + (size_t)((t + 1) & 1) * Bsz * Hsz;

        // [v | gh] = h @ [Wa | W_hh^T]   (N=2048, 256 CTAs)
        launch_gemm(hc, p_BigB, p_vgh, Bsz, NB, Hsz, 0, nullptr, NB, 1, 0);

        day_attn_kernel<<<Bsz * NDAYS, 256>>>(numpair);
        gru_gates_kernel<<<(Bsz * Hsz + 255) / 256, 256>>>(hc, hn, b_hh, t);

        // u = h_new @ Wa  (split-K 2; combine fused into week_attn)
        launch_gemm(hn, Wa, p_P, Bsz, Hsz, Hsz, 0, nullptr, Hsz, 2, SSTR);
        week_attn_kernel<<<Bsz, 128>>>(hn);

        // proj = tanh(cc @ wa_W^T)  (K=1024, split-K 2)
        launch_gemm(p_cc, wa_W, p_P, Bsz, Hsz, 2 * Hsz, 1, nullptr, Hsz, 2, SSTR);
        combine_kernel<<<(Bsz * Hsz + 255) / 256, 256>>>(p_proj, p_P, Bsz * Hsz, 1);

        // logits -> out[:, t, :]
        launch_gemm(p_proj, fc_W, out + (size_t)t * Vsz, Bsz, Vsz, Hsz, 1,
                    fc_b, Tsz * Vsz, 1, 0);
        log_softmax_kernel<<<Bsz, 256>>>(out, t);
    }

    if (out_size >= Bsz * Tsz * Vsz + Bsz)
        write_lastin_kernel<<<2, 256>>>(label, out);
}

// round 12
// speedup vs baseline: 2.6115x; 1.0061x over previous
#include <cuda_runtime.h>
#include <cuda_bf16.h>

#define Bsz 512
#define Ssz 140
#define Hsz 512
#define Esz 256
#define Vsz 1000
#define Tsz 21
#define NDAYS 7
#define DLEN 20
#define H3 (3*Hsz)
#define SOS 2
#define NB 2048    // width of [Wa | W_hh^T]
#define BM 128     // CTA tile M
#define BN 64      // CTA tile N
#define SMPA 136   // As row stride (conflict-free mma fragment loads)
#define SMPB 72    // Bs row stride

// ---------------- device scratch (allocation-free) ----------------
__device__ float g_h[2*Bsz*Hsz];            // double-buffered hidden state
__device__ float g_vgh[Bsz*NB];             // [v | gh] per batch row
__device__ float g_EW[Vsz*H3];              // emb @ W_ih^T + b_ih
__device__ float g_BigB[Hsz*NB];            // [Wa | W_hh^T]
__device__ float g_P[2*Bsz*Hsz];            // split-K partials (u / proj)
__device__ float g_Pfc[2*Bsz*1024];         // split-K partials (fc, ldc=1024)
__device__ int   g_idx[Tsz*Bsz];            // embedding row per (t,b)
__device__ float g_week[Bsz*NDAYS*Hsz];     // day contexts
__device__ float g_cc[Bsz*2*Hsz];           // [h_new, ctx]
__device__ float g_proj[Bsz*Hsz];           // tanh(cc @ wa_W^T)
__device__ __nv_bfloat16 g_encbf[(size_t)Bsz*Ssz*Hsz];  // 73.4 MB (L2-resident)

// ---------------- tf32 helpers ----------------
__device__ __forceinline__ float tf32r(float x)
{
    asm("cvt.rna.tf32.f32 %0, %0;" : "+f"(x));
    return x;
}

__device__ __forceinline__ void mma8(float (&d)[4], const unsigned (&a)[4],
                                     unsigned b0, unsigned b1)
{
    asm("mma.sync.aligned.m16n8k8.row.col.f32.tf32.tf32.f32 "
        "{%0,%1,%2,%3},{%4,%5,%6,%7},{%8,%9},{%0,%1,%2,%3};"
        : "+f"(d[0]), "+f"(d[1]), "+f"(d[2]), "+f"(d[3])
        : "r"(a[0]), "r"(a[1]), "r"(a[2]), "r"(a[3]), "r"(b0), "r"(b1));
}

// ---------------- one-time setup kernels ----------------
__global__ void build_idx_kernel(const int* __restrict__ label)
{
    int m = blockIdx.x * blockDim.x + threadIdx.x;
    if (m >= Tsz * Bsz) return;
    int t = m / Bsz, b = m % Bsz;
    g_idx[m] = (t == 0) ? SOS : label[b * (Tsz + 1) + (t - 1)];
}

__global__ void build_bigB_kernel(const float* __restrict__ Wa,
                                  const float* __restrict__ W_hh)
{
    int i = blockIdx.x * blockDim.x + threadIdx.x;
    if (i >= Hsz * NB) return;
    int k = i >> 11, n = i & (NB - 1);
    g_BigB[i] = (n < Hsz) ? Wa[k * Hsz + n]
                          : W_hh[(size_t)(n - Hsz) * Hsz + k];
}

__global__ void conv_bf16_kernel(const float* __restrict__ enc)
{
    size_t i = (size_t)blockIdx.x * blockDim.x + threadIdx.x;
    if (i >= ((size_t)Bsz * Ssz * Hsz) / 2) return;
    float2 f = *(const float2*)(enc + i * 2);
    ((__nv_bfloat162*)g_encbf)[i] = __floats2bfloat162_rn(f.x, f.y);
}

// ---------------- tf32 tensor-core GEMM ----------------
// 128x64 tile, BK=16, 256 thr = 8 warps in 4(m) x 2(n) grid; each warp owns
// a 32x32 sub-tile (mi in {0,1} m16 halves, ni in 0..3 n8 slices).
// transB=1: B is [N,K] row-major (C = A*B^T); transB=0: B is [K,N] row-major.
// gridDim.z>1: split-K; block z handles K-slice z, writes C + z*splitStride.
__global__ __launch_bounds__(256)
void tgemm(const float* __restrict__ A, const float* __restrict__ Bm,
           float* __restrict__ C, int M, int N, int K, int transB,
           const float* __restrict__ bias, int ldc, size_t splitStride)
{
    __shared__ float As[2][16][SMPA];
    __shared__ float Bs[2][16][SMPB];
    int tid = threadIdx.x;
    int bm = blockIdx.y * BM, bn = blockIdx.x * BN;
    int Kh = K / gridDim.z;
    int kbase = blockIdx.z * Kh;
    C += (size_t)blockIdx.z * splitStride;

    int lane = tid & 31, warp = tid >> 5;             // warp 0..7
    int wm = (warp & 3) * 32, wn = (warp >> 2) * 32;  // 4x2 warp grid
    int gr = lane >> 2, tg = lane & 3;

    int arow = tid >> 2, akc = (tid & 3) << 2;   // A loader (rows arow, arow+64)
    int bkr  = tid >> 4, bnc = (tid & 15) << 2;  // B non-trans loader
    int brow = tid >> 2, bkc = (tid & 3) << 2;   // B trans loader

    const float4 zero4 = make_float4(0.f, 0.f, 0.f, 0.f);
    float4 aR0, aR1, bR;

    // prologue: tile 0 -> buffer 0
    aR0 = (bm + arow < M)      ? *(const float4*)(A + (size_t)(bm + arow) * K + kbase + akc) : zero4;
    aR1 = (bm + arow + 64 < M) ? *(const float4*)(A + (size_t)(bm + arow + 64) * K + kbase + akc) : zero4;
    if (transB)
        bR = (bn + brow < N) ? *(const float4*)(Bm + (size_t)(bn + brow) * K + kbase + bkc) : zero4;
    else
        bR = (bn + bnc < N) ? *(const float4*)(Bm + (size_t)(kbase + bkr) * N + bn + bnc) : zero4;
    As[0][akc + 0][arow] = tf32r(aR0.x); As[0][akc + 1][arow] = tf32r(aR0.y);
    As[0][akc + 2][arow] = tf32r(aR0.z); As[0][akc + 3][arow] = tf32r(aR0.w);
    As[0][akc + 0][arow + 64] = tf32r(aR1.x); As[0][akc + 1][arow + 64] = tf32r(aR1.y);
    As[0][akc + 2][arow + 64] = tf32r(aR1.z); As[0][akc + 3][arow + 64] = tf32r(aR1.w);
    if (transB) {
        Bs[0][bkc + 0][brow] = tf32r(bR.x); Bs[0][bkc + 1][brow] = tf32r(bR.y);
        Bs[0][bkc + 2][brow] = tf32r(bR.z); Bs[0][bkc + 3][brow] = tf32r(bR.w);
    } else {
        Bs[0][bkr][bnc + 0] = tf32r(bR.x); Bs[0][bkr][bnc + 1] = tf32r(bR.y);
        Bs[0][bkr][bnc + 2] = tf32r(bR.z); Bs[0][bkr][bnc + 3] = tf32r(bR.w);
    }
    __syncthreads();

    float acc[2][4][4];
#pragma unroll
    for (int mi = 0; mi < 2; mi++)
#pragma unroll
        for (int ni = 0; ni < 4; ni++)
#pragma unroll
            for (int q = 0; q < 4; q++) acc[mi][ni][q] = 0.f;

    int nt = Kh >> 4;
    for (int kt = 0; kt < nt; kt++) {
        int cur = kt & 1;
        bool more = (kt + 1 < nt);
        if (more) {
            int kp = kbase + ((kt + 1) << 4);
            aR0 = (bm + arow < M)      ? *(const float4*)(A + (size_t)(bm + arow) * K + kp + akc) : zero4;
            aR1 = (bm + arow + 64 < M) ? *(const float4*)(A + (size_t)(bm + arow + 64) * K + kp + akc) : zero4;
            if (transB)
                bR = (bn + brow < N) ? *(const float4*)(Bm + (size_t)(bn + brow) * K + kp + bkc) : zero4;
            else
                bR = (bn + bnc < N) ? *(const float4*)(Bm + (size_t)(kp + bkr) * N + bn + bnc) : zero4;
        }
#pragma unroll
        for (int ks = 0; ks < 2; ks++) {
            int k0 = ks << 3;
            unsigned afr[2][4];
#pragma unroll
            for (int mi = 0; mi < 2; mi++) {
                int rm = wm + mi * 16 + gr;
                afr[mi][0] = __float_as_uint(As[cur][k0 + tg][rm]);
                afr[mi][1] = __float_as_uint(As[cur][k0 + tg][rm + 8]);
                afr[mi][2] = __float_as_uint(As[cur][k0 + tg + 4][rm]);
                afr[mi][3] = __float_as_uint(As[cur][k0 + tg + 4][rm + 8]);
            }
#pragma unroll
            for (int ni = 0; ni < 4; ni++) {
                int cn = wn + ni * 8 + gr;
                unsigned b0 = __float_as_uint(Bs[cur][k0 + tg][cn]);
                unsigned b1 = __float_as_uint(Bs[cur][k0 + tg + 4][cn]);
                mma8(acc[0][ni], afr[0], b0, b1);
                mma8(acc[1][ni], afr[1], b0, b1);
            }
        }
        if (more) {
            int nx = cur ^ 1;
            As[nx][akc + 0][arow] = tf32r(aR0.x); As[nx][akc + 1][arow] = tf32r(aR0.y);
            As[nx][akc + 2][arow] = tf32r(aR0.z); As[nx][akc + 3][arow] = tf32r(aR0.w);
            As[nx][akc + 0][arow + 64] = tf32r(aR1.x); As[nx][akc + 1][arow + 64] = tf32r(aR1.y);
            As[nx][akc + 2][arow + 64] = tf32r(aR1.z); As[nx][akc + 3][arow + 64] = tf32r(aR1.w);
            if (transB) {
                Bs[nx][bkc + 0][brow] = tf32r(bR.x); Bs[nx][bkc + 1][brow] = tf32r(bR.y);
                Bs[nx][bkc + 2][brow] = tf32r(bR.z); Bs[nx][bkc + 3][brow] = tf32r(bR.w);
            } else {
                Bs[nx][bkr][bnc + 0] = tf32r(bR.x); Bs[nx][bkr][bnc + 1] = tf32r(bR.y);
                Bs[nx][bkr][bnc + 2] = tf32r(bR.z); Bs[nx][bkr][bnc + 3] = tf32r(bR.w);
            }
        }
        __syncthreads();
    }

    // epilogue: mma C-fragment layout -> global
#pragma unroll
    for (int mi = 0; mi < 2; mi++) {
        int r0 = bm + wm + mi * 16 + gr;
        int r1 = r0 + 8;
#pragma unroll
        for (int ni = 0; ni < 4; ni++) {
            int c0 = bn + wn + ni * 8 + 2 * tg;
            float bb0 = bias ? bias[min(c0, N - 1)] : 0.f;
            float bb1 = bias ? bias[min(c0 + 1, N - 1)] : 0.f;
            if (r0 < M) {
                if (c0 < N)     C[(size_t)r0 * ldc + c0]     = acc[mi][ni][0] + bb0;
                if (c0 + 1 < N) C[(size_t)r0 * ldc + c0 + 1] = acc[mi][ni][1] + bb1;
            }
            if (r1 < M) {
                if (c0 < N)     C[(size_t)r1 * ldc + c0]     = acc[mi][ni][2] + bb0;
                if (c0 + 1 < N) C[(size_t)r1 * ldc + c0 + 1] = acc[mi][ni][3] + bb1;
            }
        }
    }
}

// ---------------- split-K combine (tanh) for proj ----------------
__global__ void combine_kernel(float* __restrict__ dst, const float* __restrict__ P,
                               int n, int doTanh)
{
    int i = blockIdx.x * blockDim.x + threadIdx.x;
    if (i >= n) return;
    float v = P[i] + P[i + n];
    dst[i] = doTanh ? tanhf(v) : v;
}

// ---------------- fused: day-level attention + GRU gates ----------------
// blocks [0, Bsz*NDAYS): day attention; blocks >= Bsz*NDAYS: GRU gates.
__global__ __launch_bounds__(256)
void day_gates_kernel(const int* __restrict__ numpairs,
                      const float* __restrict__ hcur, float* __restrict__ hnew,
                      const float* __restrict__ b_hh, int t)
{
    __shared__ float sv[Hsz];
    __shared__ __align__(16) __nv_bfloat16 tile[DLEN * Hsz];
    __shared__ float ssc[DLEN];
    __shared__ float swt[DLEN];
    int tid = threadIdx.x;

    if (blockIdx.x >= Bsz * NDAYS) {
        // ---- GRU gates ----
        int i = (blockIdx.x - Bsz * NDAYS) * 256 + tid;
        if (i >= Bsz * Hsz) return;
        int b = i >> 9, j = i & 511;
        const float* gi = g_EW + (size_t)g_idx[t * Bsz + b] * H3;
        const float* gh = g_vgh + (size_t)b * NB + Hsz;
        float ir = gi[j], iz = gi[j + Hsz], inn = gi[j + 2 * Hsz];
        float hr = gh[j] + b_hh[j];
        float hz = gh[j + Hsz] + b_hh[j + Hsz];
        float hn_ = gh[j + 2 * Hsz] + b_hh[j + 2 * Hsz];
        float r = 1.f / (1.f + expf(-(ir + hr)));
        float z = 1.f / (1.f + expf(-(iz + hz)));
        float n = tanhf(inn + r * hn_);
        hnew[i] = (1.f - z) * n + z * hcur[i];
        return;
    }

    // ---- day attention ----
    int b = blockIdx.x / NDAYS, d = blockIdx.x % NDAYS;
    for (int i = tid; i < Hsz; i += 256) sv[i] = g_vgh[(size_t)b * NB + i];
    const uint4* ep = (const uint4*)(g_encbf + ((size_t)b * Ssz + d * DLEN) * Hsz);
    uint4* tp = (uint4*)tile;
#pragma unroll
    for (int i = tid; i < DLEN * Hsz * 2 / 16; i += 256) tp[i] = ep[i];
    __syncthreads();

    int warp = tid >> 5, lane = tid & 31;
    const __nv_bfloat162* t2 = (const __nv_bfloat162*)tile;
    for (int s = warp; s < DLEN; s += 8) {
        float p = 0.f;
        for (int hp = lane; hp < Hsz / 2; hp += 32) {
            float2 cv = __bfloat1622float2(t2[s * (Hsz / 2) + hp]);
            p += sv[2 * hp] * cv.x + sv[2 * hp + 1] * cv.y;
        }
#pragma unroll
        for (int o = 16; o > 0; o >>= 1) p += __shfl_xor_sync(0xffffffffu, p, o);
        if (lane == 0) ssc[s] = p;
    }
    __syncthreads();
    if (tid < 32) {
        float val = -1e30f;
        if (tid < DLEN)
            val = (numpairs[b * Ssz + d * DLEN + tid] != 0) ? ssc[tid] : -1e9f;
        float mx = val;
#pragma unroll
        for (int o = 16; o > 0; o >>= 1) mx = fmaxf(mx, __shfl_xor_sync(0xffffffffu, mx, o));
        float e = (tid < DLEN) ? expf(val - mx) : 0.f;
        float sm = e;
#pragma unroll
        for (int o = 16; o > 0; o >>= 1) sm += __shfl_xor_sync(0xffffffffu, sm, o);
        if (tid < DLEN) swt[tid] = e / sm;
    }
    __syncthreads();
    {
        int hp = tid;
        float2 a = make_float2(0.f, 0.f);
#pragma unroll
        for (int s = 0; s < DLEN; s++) {
            float2 cv = __bfloat1622float2(t2[s * (Hsz / 2) + hp]);
            a.x += swt[s] * cv.x;
            a.y += swt[s] * cv.y;
        }
        float* wk = g_week + ((size_t)b * NDAYS + d) * Hsz;
        wk[2 * hp] = a.x;
        wk[2 * hp + 1] = a.y;
    }
}

// ---------------- week-level attention + concat (u combine fused) ----------------
__global__ void week_attn_kernel(const float* __restrict__ hnew)
{
    __shared__ float su[Hsz];
    __shared__ float sc[8];
    __shared__ float aw[8];
    int b = blockIdx.x, tid = threadIdx.x;  // 128 threads
    const size_t SSTR = (size_t)Bsz * Hsz;
    for (int i = tid; i < Hsz; i += 128)
        su[i] = g_P[(size_t)b * Hsz + i] + g_P[SSTR + (size_t)b * Hsz + i];
    __syncthreads();
    int warp = tid >> 5, lane = tid & 31;
    for (int d = warp; d < NDAYS; d += 4) {
        const float* w = g_week + ((size_t)b * NDAYS + d) * Hsz;
        float p = 0.f;
        for (int h = lane; h < Hsz; h += 32) p += su[h] * w[h];
#pragma unroll
        for (int o = 16; o > 0; o >>= 1) p += __shfl_xor_sync(0xffffffffu, p, o);
        if (lane == 0) sc[d] = p;
    }
    __syncthreads();
    if (tid == 0) {
        float mx = -1e30f;
        for (int d = 0; d < NDAYS; d++) mx = fmaxf(mx, sc[d]);
        float e[NDAYS], s = 0.f;
        for (int d = 0; d < NDAYS; d++) { e[d] = expf(sc[d] - mx); s += e[d]; }
        for (int d = 0; d < NDAYS; d++) aw[d] = e[d] / s;
    }
    __syncthreads();
    for (int h = tid; h < Hsz; h += 128) {
        float c = 0.f;
#pragma unroll
        for (int d = 0; d < NDAYS; d++)
            c += aw[d] * g_week[((size_t)b * NDAYS + d) * Hsz + h];
        g_cc[(size_t)b * 2 * Hsz + Hsz + h] = c;
        g_cc[(size_t)b * 2 * Hsz + h] = hnew[b * Hsz + h];
    }
}

// ---------------- fused fc split-K combine + bias + log_softmax ----------------
__global__ __launch_bounds__(256)
void fc_softmax_kernel(const float* __restrict__ fc_b, float* __restrict__ out, int t)
{
    __shared__ float sred[8];
    int b = blockIdx.x, tid = threadIdx.x;
    const float* P0 = g_Pfc + (size_t)b * 1024;
    const float* P1 = g_Pfc + (size_t)Bsz * 1024 + (size_t)b * 1024;

    float lv[4];
    float mx = -1e30f;
#pragma unroll
    for (int q = 0; q < 4; q++) {
        int i = tid + q * 256;
        float v = -1e30f;
        if (i < Vsz) v = P0[i] + P1[i] + fc_b[i];
        lv[q] = v;
        mx = fmaxf(mx, v);
    }
#pragma unroll
    for (int o = 16; o > 0; o >>= 1) mx = fmaxf(mx, __shfl_xor_sync(0xffffffffu, mx, o));
    if ((tid & 31) == 0) sred[tid >> 5] = mx;
    __syncthreads();
    if (tid == 0) {
        float m = sred[0];
        for (int i = 1; i < 8; i++) m = fmaxf(m, sred[i]);
        sred[0] = m;
    }
    __syncthreads();
    mx = sred[0];
    __syncthreads();
    float s = 0.f;
#pragma unroll
    for (int q = 0; q < 4; q++)
        if (tid + q * 256 < Vsz) s += expf(lv[q] - mx);
#pragma unroll
    for (int o = 16; o > 0; o >>= 1) s += __shfl_xor_sync(0xffffffffu, s, o);
    if ((tid & 31) == 0) sred[tid >> 5] = s;
    __syncthreads();
    if (tid == 0) {
        float ss = 0.f;
        for (int i = 0; i < 8; i++) ss += sred[i];
        sred[0] = mx + logf(ss);
    }
    __syncthreads();
    float lse = sred[0];
    float* row = out + ((size_t)b * Tsz + t) * Vsz;
#pragma unroll
    for (int q = 0; q < 4; q++) {
        int i = tid + q * 256;
        if (i < Vsz) row[i] = lv[q] - lse;
    }
}

__global__ void write_lastin_kernel(const int* __restrict__ label,
                                    float* __restrict__ out)
{
    int b = blockIdx.x * blockDim.x + threadIdx.x;
    if (b < Bsz)
        out[(size_t)Bsz * Tsz * Vsz + b] = (float)label[b * (Tsz + 1) + (Tsz - 1)];
}

// ---------------- host orchestration ----------------
static void launch_gemm(const float* A, const float* Bm, float* C,
                        int M, int N, int K, int transB, const float* bias,
                        int ldc, int splitZ, size_t splitStride)
{
    dim3 grid((N + BN - 1) / BN, (M + BM - 1) / BM, splitZ);
    tgemm<<<grid, 256>>>(A, Bm, C, M, N, K, transB, bias, ldc, splitStride);
}

extern "C" void kernel_launch(void* const* d_in, const int* in_sizes, int n_in,
                              void* d_out, int out_size)
{
    const float* enc_h   = (const float*)d_in[0];
    const float* enc_o   = (const float*)d_in[1];
    const int*   label   = (const int*)d_in[2];
    const int*   numpair = (const int*)d_in[3];
    const float* emb     = (const float*)d_in[4];
    const float* W_ih    = (const float*)d_in[5];
    const float* W_hh    = (const float*)d_in[6];
    const float* b_ih    = (const float*)d_in[7];
    const float* b_hh    = (const float*)d_in[8];
    const float* Wa      = (const float*)d_in[9];
    const float* wa_W    = (const float*)d_in[10];
    const float* fc_W    = (const float*)d_in[11];
    const float* fc_b    = (const float*)d_in[12];
    float* out = (float*)d_out;

    float *p_h, *p_vgh, *p_EW, *p_BigB, *p_P, *p_Pfc, *p_cc, *p_proj;
    cudaGetSymbolAddress((void**)&p_h,    g_h);
    cudaGetSymbolAddress((void**)&p_vgh,  g_vgh);
    cudaGetSymbolAddress((void**)&p_EW,   g_EW);
    cudaGetSymbolAddress((void**)&p_BigB, g_BigB);
    cudaGetSymbolAddress((void**)&p_P,    g_P);
    cudaGetSymbolAddress((void**)&p_Pfc,  g_Pfc);
    cudaGetSymbolAddress((void**)&p_cc,   g_cc);
    cudaGetSymbolAddress((void**)&p_proj, g_proj);

    // h0 = encoder_hidden[0]
    cudaMemcpyAsync(p_h, enc_h, (size_t)Bsz * Hsz * sizeof(float),
                    cudaMemcpyDeviceToDevice);

    // one-time setup
    build_idx_kernel<<<(Tsz * Bsz + 255) / 256, 256>>>(label);
    build_bigB_kernel<<<(Hsz * NB + 255) / 256, 256>>>(Wa, W_hh);
    conv_bf16_kernel<<<(int)(((size_t)Bsz * Ssz * Hsz / 2 + 255) / 256), 256>>>(enc_o);
    // EW = emb @ W_ih^T + b_ih   [1000 x 1536]
    launch_gemm(emb, W_ih, p_EW, Vsz, H3, Esz, 1, b_ih, H3, 1, 0);

    const size_t SSTR = (size_t)Bsz * Hsz;
    const int DG_GRID = Bsz * NDAYS + (Bsz * Hsz) / 256;

    for (int t = 0; t < Tsz; t++) {
        float* hc = p_h + (size_t)(t & 1) * Bsz * Hsz;
        float* hn = p_h + (size_t)((t + 1) & 1) * Bsz * Hsz;

        // [v | gh] = h @ [Wa | W_hh^T]   (N=2048, 128 CTAs)
        launch_gemm(hc, p_BigB, p_vgh, Bsz, NB, Hsz, 0, nullptr, NB, 1, 0);

        // day attention + GRU gates in one launch
        day_gates_kernel<<<DG_GRID, 256>>>(numpair, hc, hn, b_hh, t);

        // u = h_new @ Wa  (split-K 2; combine fused into week_attn)
        launch_gemm(hn, Wa, p_P, Bsz, Hsz, Hsz, 0, nullptr, Hsz, 2, SSTR);
        week_attn_kernel<<<Bsz, 128>>>(hn);

        // proj = tanh(cc @ wa_W^T)  (K=1024, split-K 2)
        launch_gemm(p_cc, wa_W, p_P, Bsz, Hsz, 2 * Hsz, 1, nullptr, Hsz, 2, SSTR);
        combine_kernel<<<(Bsz * Hsz + 255) / 256, 256>>>(p_proj, p_P, Bsz * Hsz, 1);

        // logits (split-K 2, partials; bias+combine+log_softmax fused)
        launch_gemm(p_proj, fc_W, p_Pfc, Bsz, Vsz, Hsz, 1, nullptr, 1024,
                    2, (size_t)Bsz * 1024);
        fc_softmax_kernel<<<Bsz, 256>>>(fc_b, out, t);
    }

    if (out_size >= Bsz * Tsz * Vsz + Bsz)
        write_lastin_kernel<<<2, 256>>>(label, out);
}

// round 14
// speedup vs baseline: 3.6085x; 1.3818x over previous
#include <cuda_runtime.h>
#include <cuda_bf16.h>

#define Bsz 512
#define Ssz 140
#define Hsz 512
#define Esz 256
#define Vsz 1000
#define Tsz 21
#define NDAYS 7
#define DLEN 20
#define H3 (3*Hsz)
#define SOS 2
#define NB 2048    // width of [Wa | W_hh^T]
#define BM 128     // CTA tile M
#define BN 64      // CTA tile N
#define SMPA 136   // As row stride (conflict-free mma fragment loads)
#define SMPB 72    // Bs row stride

// ---------------- device scratch (allocation-free) ----------------
__device__ float g_h[2*Bsz*Hsz];            // double-buffered hidden state
__device__ float g_vgh[2*Bsz*NB];           // [v|gh] split-K partials (2 slices)
__device__ float g_EW[Vsz*H3];              // emb @ W_ih^T + b_ih
__device__ float g_BigB[Hsz*NB];            // [Wa | W_hh^T]
__device__ float g_P[4*Bsz*Hsz];            // proj split-K partials (4 slices)
__device__ float g_Pfc[4*Bsz*1024];         // fc split-K partials (4 slices)
__device__ int   g_idx[Tsz*Bsz];            // embedding row per (t,b)
__device__ float g_week[Bsz*NDAYS*Hsz];     // day contexts
__device__ float g_cc[Bsz*2*Hsz];           // [h_new, ctx]
__device__ float g_proj[Bsz*Hsz];           // tanh(cc @ wa_W^T)
__device__ __nv_bfloat16 g_encbf[(size_t)Bsz*Ssz*Hsz];  // 73.4 MB (L2-resident)

#define VGH_STR ((size_t)Bsz*NB)

// ---------------- tf32 helpers ----------------
__device__ __forceinline__ float tf32r(float x)
{
    asm("cvt.rna.tf32.f32 %0, %0;" : "+f"(x));
    return x;
}

__device__ __forceinline__ void mma8(float (&d)[4], const unsigned (&a)[4],
                                     unsigned b0, unsigned b1)
{
    asm("mma.sync.aligned.m16n8k8.row.col.f32.tf32.tf32.f32 "
        "{%0,%1,%2,%3},{%4,%5,%6,%7},{%8,%9},{%0,%1,%2,%3};"
        : "+f"(d[0]), "+f"(d[1]), "+f"(d[2]), "+f"(d[3])
        : "r"(a[0]), "r"(a[1]), "r"(a[2]), "r"(a[3]), "r"(b0), "r"(b1));
}

// ---------------- one-time setup kernels ----------------
__global__ void build_idx_kernel(const int* __restrict__ label)
{
    int m = blockIdx.x * blockDim.x + threadIdx.x;
    if (m >= Tsz * Bsz) return;
    int t = m / Bsz, b = m % Bsz;
    g_idx[m] = (t == 0) ? SOS : label[b * (Tsz + 1) + (t - 1)];
}

__global__ void build_bigB_kernel(const float* __restrict__ Wa,
                                  const float* __restrict__ W_hh)
{
    int i = blockIdx.x * blockDim.x + threadIdx.x;
    if (i >= Hsz * NB) return;
    int k = i >> 11, n = i & (NB - 1);
    g_BigB[i] = (n < Hsz) ? Wa[k * Hsz + n]
                          : W_hh[(size_t)(n - Hsz) * Hsz + k];
}

__global__ void conv_bf16_kernel(const float* __restrict__ enc)
{
    size_t i = (size_t)blockIdx.x * blockDim.x + threadIdx.x;
    if (i >= ((size_t)Bsz * Ssz * Hsz) / 2) return;
    float2 f = *(const float2*)(enc + i * 2);
    ((__nv_bfloat162*)g_encbf)[i] = __floats2bfloat162_rn(f.x, f.y);
}

// ---------------- tf32 tensor-core GEMM ----------------
// 128x64 tile, BK=16, 256 thr = 8 warps in 4(m) x 2(n) grid; warp tile 32x32.
// transB=1: B is [N,K] row-major (C = A*B^T); transB=0: B is [K,N] row-major.
// gridDim.z>1: split-K; block z handles K-slice z, writes C + z*splitStride.
__global__ __launch_bounds__(256)
void tgemm(const float* __restrict__ A, const float* __restrict__ Bm,
           float* __restrict__ C, int M, int N, int K, int transB,
           const float* __restrict__ bias, int ldc, size_t splitStride)
{
    __shared__ float As[2][16][SMPA];
    __shared__ float Bs[2][16][SMPB];
    int tid = threadIdx.x;
    int bm = blockIdx.y * BM, bn = blockIdx.x * BN;
    int Kh = K / gridDim.z;
    int kbase = blockIdx.z * Kh;
    C += (size_t)blockIdx.z * splitStride;

    int lane = tid & 31, warp = tid >> 5;             // warp 0..7
    int wm = (warp & 3) * 32, wn = (warp >> 2) * 32;  // 4x2 warp grid
    int gr = lane >> 2, tg = lane & 3;

    int arow = tid >> 2, akc = (tid & 3) << 2;   // A loader (rows arow, arow+64)
    int bkr  = tid >> 4, bnc = (tid & 15) << 2;  // B non-trans loader
    int brow = tid >> 2, bkc = (tid & 3) << 2;   // B trans loader

    const float4 zero4 = make_float4(0.f, 0.f, 0.f, 0.f);
    float4 aR0, aR1, bR;

    // prologue: tile 0 -> buffer 0
    aR0 = (bm + arow < M)      ? *(const float4*)(A + (size_t)(bm + arow) * K + kbase + akc) : zero4;
    aR1 = (bm + arow + 64 < M) ? *(const float4*)(A + (size_t)(bm + arow + 64) * K + kbase + akc) : zero4;
    if (transB)
        bR = (bn + brow < N) ? *(const float4*)(Bm + (size_t)(bn + brow) * K + kbase + bkc) : zero4;
    else
        bR = (bn + bnc < N) ? *(const float4*)(Bm + (size_t)(kbase + bkr) * N + bn + bnc) : zero4;
    As[0][akc + 0][arow] = tf32r(aR0.x); As[0][akc + 1][arow] = tf32r(aR0.y);
    As[0][akc + 2][arow] = tf32r(aR0.z); As[0][akc + 3][arow] = tf32r(aR0.w);
    As[0][akc + 0][arow + 64] = tf32r(aR1.x); As[0][akc + 1][arow + 64] = tf32r(aR1.y);
    As[0][akc + 2][arow + 64] = tf32r(aR1.z); As[0][akc + 3][arow + 64] = tf32r(aR1.w);
    if (transB) {
        Bs[0][bkc + 0][brow] = tf32r(bR.x); Bs[0][bkc + 1][brow] = tf32r(bR.y);
        Bs[0][bkc + 2][brow] = tf32r(bR.z); Bs[0][bkc + 3][brow] = tf32r(bR.w);
    } else {
        Bs[0][bkr][bnc + 0] = tf32r(bR.x); Bs[0][bkr][bnc + 1] = tf32r(bR.y);
        Bs[0][bkr][bnc + 2] = tf32r(bR.z); Bs[0][bkr][bnc + 3] = tf32r(bR.w);
    }
    __syncthreads();

    float acc[2][4][4];
#pragma unroll
    for (int mi = 0; mi < 2; mi++)
#pragma unroll
        for (int ni = 0; ni < 4; ni++)
#pragma unroll
            for (int q = 0; q < 4; q++) acc[mi][ni][q] = 0.f;

    int nt = Kh >> 4;
    for (int kt = 0; kt < nt; kt++) {
        int cur = kt & 1;
        bool more = (kt + 1 < nt);
        if (more) {
            int kp = kbase + ((kt + 1) << 4);
            aR0 = (bm + arow < M)      ? *(const float4*)(A + (size_t)(bm + arow) * K + kp + akc) : zero4;
            aR1 = (bm + arow + 64 < M) ? *(const float4*)(A + (size_t)(bm + arow + 64) * K + kp + akc) : zero4;
            if (transB)
                bR = (bn + brow < N) ? *(const float4*)(Bm + (size_t)(bn + brow) * K + kp + bkc) : zero4;
            else
                bR = (bn + bnc < N) ? *(const float4*)(Bm + (size_t)(kp + bkr) * N + bn + bnc) : zero4;
        }
#pragma unroll
        for (int ks = 0; ks < 2; ks++) {
            int k0 = ks << 3;
            unsigned afr[2][4];
#pragma unroll
            for (int mi = 0; mi < 2; mi++) {
                int rm = wm + mi * 16 + gr;
                afr[mi][0] = __float_as_uint(As[cur][k0 + tg][rm]);
                afr[mi][1] = __float_as_uint(As[cur][k0 + tg][rm + 8]);
                afr[mi][2] = __float_as_uint(As[cur][k0 + tg + 4][rm]);
                afr[mi][3] = __float_as_uint(As[cur][k0 + tg + 4][rm + 8]);
            }
#pragma unroll
            for (int ni = 0; ni < 4; ni++) {
                int cn = wn + ni * 8 + gr;
                unsigned b0 = __float_as_uint(Bs[cur][k0 + tg][cn]);
                unsigned b1 = __float_as_uint(Bs[cur][k0 + tg + 4][cn]);
                mma8(acc[0][ni], afr[0], b0, b1);
                mma8(acc[1][ni], afr[1], b0, b1);
            }
        }
        if (more) {
            int nx = cur ^ 1;
            As[nx][akc + 0][arow] = tf32r(aR0.x); As[nx][akc + 1][arow] = tf32r(aR0.y);
            As[nx][akc + 2][arow] = tf32r(aR0.z); As[nx][akc + 3][arow] = tf32r(aR0.w);
            As[nx][akc + 0][arow + 64] = tf32r(aR1.x); As[nx][akc + 1][arow + 64] = tf32r(aR1.y);
            As[nx][akc + 2][arow + 64] = tf32r(aR1.z); As[nx][akc + 3][arow + 64] = tf32r(aR1.w);
            if (transB) {
                Bs[nx][bkc + 0][brow] = tf32r(bR.x); Bs[nx][bkc + 1][brow] = tf32r(bR.y);
                Bs[nx][bkc + 2][brow] = tf32r(bR.z); Bs[nx][bkc + 3][brow] = tf32r(bR.w);
            } else {
                Bs[nx][bkr][bnc + 0] = tf32r(bR.x); Bs[nx][bkr][bnc + 1] = tf32r(bR.y);
                Bs[nx][bkr][bnc + 2] = tf32r(bR.z); Bs[nx][bkr][bnc + 3] = tf32r(bR.w);
            }
        }
        __syncthreads();
    }

    // epilogue: mma C-fragment layout -> global
#pragma unroll
    for (int mi = 0; mi < 2; mi++) {
        int r0 = bm + wm + mi * 16 + gr;
        int r1 = r0 + 8;
#pragma unroll
        for (int ni = 0; ni < 4; ni++) {
            int c0 = bn + wn + ni * 8 + 2 * tg;
            float bb0 = bias ? bias[min(c0, N - 1)] : 0.f;
            float bb1 = bias ? bias[min(c0 + 1, N - 1)] : 0.f;
            if (r0 < M) {
                if (c0 < N)     C[(size_t)r0 * ldc + c0]     = acc[mi][ni][0] + bb0;
                if (c0 + 1 < N) C[(size_t)r0 * ldc + c0 + 1] = acc[mi][ni][1] + bb1;
            }
            if (r1 < M) {
                if (c0 < N)     C[(size_t)r1 * ldc + c0]     = acc[mi][ni][2] + bb0;
                if (c0 + 1 < N) C[(size_t)r1 * ldc + c0 + 1] = acc[mi][ni][3] + bb1;
            }
        }
    }
}

// ---------------- proj combine: dst = tanh(P0+P1+P2+P3) ----------------
__global__ void combine4_kernel(float* __restrict__ dst, const float* __restrict__ P,
                                int n)
{
    int i = blockIdx.x * blockDim.x + threadIdx.x;
    if (i >= n) return;
    dst[i] = tanhf(P[i] + P[i + n] + P[i + 2 * n] + P[i + 3 * n]);
}

// ---------------- fused: day-level attention + GRU gates ----------------
// blocks [0, Bsz*NDAYS): day attention; blocks >= Bsz*NDAYS: GRU gates.
// v and gh are read as sums of the two vgh split-K partials.
__global__ __launch_bounds__(256)
void day_gates_kernel(const int* __restrict__ numpairs,
                      const float* __restrict__ hcur, float* __restrict__ hnew,
                      const float* __restrict__ b_hh, int t)
{
    __shared__ float sv[Hsz];
    __shared__ __align__(16) __nv_bfloat16 tile[DLEN * Hsz];
    __shared__ float ssc[DLEN];
    __shared__ float swt[DLEN];
    int tid = threadIdx.x;

    if (blockIdx.x >= Bsz * NDAYS) {
        // ---- GRU gates ----
        int i = (blockIdx.x - Bsz * NDAYS) * 256 + tid;
        if (i >= Bsz * Hsz) return;
        int b = i >> 9, j = i & 511;
        const float* gi = g_EW + (size_t)g_idx[t * Bsz + b] * H3;
        const float* gh0 = g_vgh + (size_t)b * NB + Hsz;
        const float* gh1 = gh0 + VGH_STR;
        float ir = gi[j], iz = gi[j + Hsz], inn = gi[j + 2 * Hsz];
        float hr = gh0[j] + gh1[j] + b_hh[j];
        float hz = gh0[j + Hsz] + gh1[j + Hsz] + b_hh[j + Hsz];
        float hn_ = gh0[j + 2 * Hsz] + gh1[j + 2 * Hsz] + b_hh[j + 2 * Hsz];
        float r = 1.f / (1.f + expf(-(ir + hr)));
        float z = 1.f / (1.f + expf(-(iz + hz)));
        float n = tanhf(inn + r * hn_);
        hnew[i] = (1.f - z) * n + z * hcur[i];
        return;
    }

    // ---- day attention ----
    int b = blockIdx.x / NDAYS, d = blockIdx.x % NDAYS;
    for (int i = tid; i < Hsz; i += 256)
        sv[i] = g_vgh[(size_t)b * NB + i] + g_vgh[VGH_STR + (size_t)b * NB + i];
    const uint4* ep = (const uint4*)(g_encbf + ((size_t)b * Ssz + d * DLEN) * Hsz);
    uint4* tp = (uint4*)tile;
#pragma unroll
    for (int i = tid; i < DLEN * Hsz * 2 / 16; i += 256) tp[i] = ep[i];
    __syncthreads();

    int warp = tid >> 5, lane = tid & 31;
    const __nv_bfloat162* t2 = (const __nv_bfloat162*)tile;
    for (int s = warp; s < DLEN; s += 8) {
        float p = 0.f;
        for (int hp = lane; hp < Hsz / 2; hp += 32) {
            float2 cv = __bfloat1622float2(t2[s * (Hsz / 2) + hp]);
            p += sv[2 * hp] * cv.x + sv[2 * hp + 1] * cv.y;
        }
#pragma unroll
        for (int o = 16; o > 0; o >>= 1) p += __shfl_xor_sync(0xffffffffu, p, o);
        if (lane == 0) ssc[s] = p;
    }
    __syncthreads();
    if (tid < 32) {
        float val = -1e30f;
        if (tid < DLEN)
            val = (numpairs[b * Ssz + d * DLEN + tid] != 0) ? ssc[tid] : -1e9f;
        float mx = val;
#pragma unroll
        for (int o = 16; o > 0; o >>= 1) mx = fmaxf(mx, __shfl_xor_sync(0xffffffffu, mx, o));
        float e = (tid < DLEN) ? expf(val - mx) : 0.f;
        float sm = e;
#pragma unroll
        for (int o = 16; o > 0; o >>= 1) sm += __shfl_xor_sync(0xffffffffu, sm, o);
        if (tid < DLEN) swt[tid] = e / sm;
    }
    __syncthreads();
    {
        int hp = tid;
        float2 a = make_float2(0.f, 0.f);
#pragma unroll
        for (int s = 0; s < DLEN; s++) {
            float2 cv = __bfloat1622float2(t2[s * (Hsz / 2) + hp]);
            a.x += swt[s] * cv.x;
            a.y += swt[s] * cv.y;
        }
        float* wk = g_week + ((size_t)b * NDAYS + d) * Hsz;
        wk[2 * hp] = a.x;
        wk[2 * hp + 1] = a.y;
    }
}

// ---------------- week-level attention + concat (u = vgh partial sum) ----------------
__global__ void week_attn_kernel(const float* __restrict__ hnew)
{
    __shared__ float su[Hsz];
    __shared__ float sc[8];
    __shared__ float aw[8];
    int b = blockIdx.x, tid = threadIdx.x;  // 128 threads
    for (int i = tid; i < Hsz; i += 128)
        su[i] = g_vgh[(size_t)b * NB + i] + g_vgh[VGH_STR + (size_t)b * NB + i];
    __syncthreads();
    int warp = tid >> 5, lane = tid & 31;
    for (int d = warp; d < NDAYS; d += 4) {
        const float* w = g_week + ((size_t)b * NDAYS + d) * Hsz;
        float p = 0.f;
        for (int h = lane; h < Hsz; h += 32) p += su[h] * w[h];
#pragma unroll
        for (int o = 16; o > 0; o >>= 1) p += __shfl_xor_sync(0xffffffffu, p, o);
        if (lane == 0) sc[d] = p;
    }
    __syncthreads();
    if (tid == 0) {
        float mx = -1e30f;
        for (int d = 0; d < NDAYS; d++) mx = fmaxf(mx, sc[d]);
        float e[NDAYS], s = 0.f;
        for (int d = 0; d < NDAYS; d++) { e[d] = expf(sc[d] - mx); s += e[d]; }
        for (int d = 0; d < NDAYS; d++) aw[d] = e[d] / s;
    }
    __syncthreads();
    for (int h = tid; h < Hsz; h += 128) {
        float c = 0.f;
#pragma unroll
        for (int d = 0; d < NDAYS; d++)
            c += aw[d] * g_week[((size_t)b * NDAYS + d) * Hsz + h];
        g_cc[(size_t)b * 2 * Hsz + Hsz + h] = c;
        g_cc[(size_t)b * 2 * Hsz + h] = hnew[b * Hsz + h];
    }
}

// ---------------- fused fc split-K4 combine + bias + log_softmax ----------------
__global__ __launch_bounds__(256)
void fc_softmax_kernel(const float* __restrict__ fc_b, float* __restrict__ out, int t)
{
    __shared__ float sred[8];
    int b = blockIdx.x, tid = threadIdx.x;
    const size_t FSTR = (size_t)Bsz * 1024;
    const float* P0 = g_Pfc + (size_t)b * 1024;

    float lv[4];
    float mx = -1e30f;
#pragma unroll
    for (int q = 0; q < 4; q++) {
        int i = tid + q * 256;
        float v = -1e30f;
        if (i < Vsz)
            v = P0[i] + P0[i + FSTR] + P0[i + 2 * FSTR] + P0[i + 3 * FSTR] + fc_b[i];
        lv[q] = v;
        mx = fmaxf(mx, v);
    }
#pragma unroll
    for (int o = 16; o > 0; o >>= 1) mx = fmaxf(mx, __shfl_xor_sync(0xffffffffu, mx, o));
    if ((tid & 31) == 0) sred[tid >> 5] = mx;
    __syncthreads();
    if (tid == 0) {
        float m = sred[0];
        for (int i = 1; i < 8; i++) m = fmaxf(m, sred[i]);
        sred[0] = m;
    }
    __syncthreads();
    mx = sred[0];
    __syncthreads();
    float s = 0.f;
#pragma unroll
    for (int q = 0; q < 4; q++)
        if (tid + q * 256 < Vsz) s += expf(lv[q] - mx);
#pragma unroll
    for (int o = 16; o > 0; o >>= 1) s += __shfl_xor_sync(0xffffffffu, s, o);
    if ((tid & 31) == 0) sred[tid >> 5] = s;
    __syncthreads();
    if (tid == 0) {
        float ss = 0.f;
        for (int i = 0; i < 8; i++) ss += sred[i];
        sred[0] = mx + logf(ss);
    }
    __syncthreads();
    float lse = sred[0];
    float* row = out + ((size_t)b * Tsz + t) * Vsz;
#pragma unroll
    for (int q = 0; q < 4; q++) {
        int i = tid + q * 256;
        if (i < Vsz) row[i] = lv[q] - lse;
    }
}

__global__ void write_lastin_kernel(const int* __restrict__ label,
                                    float* __restrict__ out)
{
    int b = blockIdx.x * blockDim.x + threadIdx.x;
    if (b < Bsz)
        out[(size_t)Bsz * Tsz * Vsz + b] = (float)label[b * (Tsz + 1) + (Tsz - 1)];
}

// ---------------- host orchestration ----------------
static void launch_gemm(const float* A, const float* Bm, float* C,
                        int M, int N, int K, int transB, const float* bias,
                        int ldc, int splitZ, size_t splitStride)
{
    dim3 grid((N + BN - 1) / BN, (M + BM - 1) / BM, splitZ);
    tgemm<<<grid, 256>>>(A, Bm, C, M, N, K, transB, bias, ldc, splitStride);
}

extern "C" void kernel_launch(void* const* d_in, const int* in_sizes, int n_in,
                              void* d_out, int out_size)
{
    const float* enc_h   = (const float*)d_in[0];
    const float* enc_o   = (const float*)d_in[1];
    const int*   label   = (const int*)d_in[2];
    const int*   numpair = (const int*)d_in[3];
    const float* emb     = (const float*)d_in[4];
    const float* W_ih    = (const float*)d_in[5];
    const float* W_hh    = (const float*)d_in[6];
    const float* b_ih    = (const float*)d_in[7];
    const float* b_hh    = (const float*)d_in[8];
    const float* Wa      = (const float*)d_in[9];
    const float* wa_W    = (const float*)d_in[10];
    const float* fc_W    = (const float*)d_in[11];
    const float* fc_b    = (const float*)d_in[12];
    float* out = (float*)d_out;

    float *p_h, *p_vgh, *p_EW, *p_BigB, *p_P, *p_Pfc, *p_cc, *p_proj;
    cudaGetSymbolAddress((void**)&p_h,    g_h);
    cudaGetSymbolAddress((void**)&p_vgh,  g_vgh);
    cudaGetSymbolAddress((void**)&p_EW,   g_EW);
    cudaGetSymbolAddress((void**)&p_BigB, g_BigB);
    cudaGetSymbolAddress((void**)&p_P,    g_P);
    cudaGetSymbolAddress((void**)&p_Pfc,  g_Pfc);
    cudaGetSymbolAddress((void**)&p_cc,   g_cc);
    cudaGetSymbolAddress((void**)&p_proj, g_proj);

    // h0 = encoder_hidden[0]
    cudaMemcpyAsync(p_h, enc_h, (size_t)Bsz * Hsz * sizeof(float),
                    cudaMemcpyDeviceToDevice);

    // one-time setup
    build_idx_kernel<<<(Tsz * Bsz + 255) / 256, 256>>>(label);
    build_bigB_kernel<<<(Hsz * NB + 255) / 256, 256>>>(Wa, W_hh);
    conv_bf16_kernel<<<(int)(((size_t)Bsz * Ssz * Hsz / 2 + 255) / 256), 256>>>(enc_o);
    // EW = emb @ W_ih^T + b_ih   [1000 x 1536]
    launch_gemm(emb, W_ih, p_EW, Vsz, H3, Esz, 1, b_ih, H3, 1, 0);

    const int DG_GRID = Bsz * NDAYS + (Bsz * Hsz) / 256;

    // initial [v0 | gh0] = h0 @ [Wa | W_hh^T]  (split-K 2)
    launch_gemm(p_h, p_BigB, p_vgh, Bsz, NB, Hsz, 0, nullptr, NB, 2, VGH_STR);

    for (int t = 0; t < Tsz; t++) {
        float* hc = p_h + (size_t)(t & 1) * Bsz * Hsz;
        float* hn = p_h + (size_t)((t + 1) & 1) * Bsz * Hsz;

        // day attention (v from vgh) + GRU gates (gh from vgh) in one launch
        day_gates_kernel<<<DG_GRID, 256>>>(numpair, hc, hn, b_hh, t);

        // [u_t | gh_{t+1}] = h_{t+1} @ [Wa | W_hh^T]  (split-K 2)
        // u_t doubles as v_{t+1} next iteration.
        launch_gemm(hn, p_BigB, p_vgh, Bsz, NB, Hsz, 0, nullptr, NB, 2, VGH_STR);

        // week attention (u from vgh partial sum) + cc build
        week_attn_kernel<<<Bsz, 128>>>(hn);

        // proj = tanh(cc @ wa_W^T)  (K=1024, split-K 4)
        launch_gemm(p_cc, wa_W, p_P, Bsz, Hsz, 2 * Hsz, 1, nullptr, Hsz,
                    4, (size_t)Bsz * Hsz);
        combine4_kernel<<<(Bsz * Hsz + 255) / 256, 256>>>(p_proj, p_P, Bsz * Hsz);

        // logits (split-K 4, partials; bias+combine+log_softmax fused)
        launch_gemm(p_proj, fc_W, p_Pfc, Bsz, Vsz, Hsz, 1, nullptr, 1024,
                    4, (size_t)Bsz * 1024);
        fc_softmax_kernel<<<Bsz, 256>>>(fc_b, out, t);
    }

    if (out_size >= Bsz * Tsz * Vsz + Bsz)
        write_lastin_kernel<<<2, 256>>>(label, out);
}